// round 2
// baseline (speedup 1.0000x reference)
#include <cuda_runtime.h>

#define EPSV 1e-5f

// ---------------- shared memory layout (float offsets) ----------------
// region1 (7168): pooled[128][56]  -> later q/k/v/attn  -> later xpadA[32][9][12]
// region2 (3456): xbuf[32][56] (first 1792) -> later xpadB[32][9][12]
// ws      (5520): w_cr (32x129) + qw/kw (4x33 each) + vw (32x33)
//                 -> later w_res half (32x145) -> later w1 (16x289) + w2 (144)
// red     (64)  : LN reduction scratch
#define R1_OFF   0
#define R2_OFF   7168
#define WS_OFF   10624
#define RED_OFF  16144
#define SMEM_FLOATS 16208

#define Q_OFF    (R1_OFF + 0)      // 4*56
#define K_OFF    (R1_OFF + 224)    // 4*56
#define V_OFF    (R1_OFF + 448)    // 32*56
#define ATT_OFF  (R1_OFF + 2240)   // 56*57 = 3192 (padded rows, stride 57)

#define WCR_OFF  (WS_OFF + 0)      // 32*129
#define QW_OFF   (WS_OFF + 4160)   // 4*33
#define KW_OFF   (WS_OFF + 4292)   // 4*33
#define VW_OFF   (WS_OFF + 4424)   // 32*33  (ends at WS_OFF+5480)

// xpad layout: channel stride 108 (9 rows * 12 cols), row stride 12, interior at [1..7][1..8]

// acc[8] += w[c*wstride] * x8[c*ldx .. +7] for c in [0,K)
__device__ __forceinline__ void gemm_row8(float acc[8], const float* __restrict__ w,
                                          int wstride, const float* __restrict__ xcol,
                                          int ldx, int K) {
    for (int c = 0; c < K; ++c) {
        float wv = w[c * wstride];
        const float4* px = (const float4*)(xcol + c * ldx);
        float4 A = px[0], B = px[1];
        acc[0] = fmaf(wv, A.x, acc[0]); acc[1] = fmaf(wv, A.y, acc[1]);
        acc[2] = fmaf(wv, A.z, acc[2]); acc[3] = fmaf(wv, A.w, acc[3]);
        acc[4] = fmaf(wv, B.x, acc[4]); acc[5] = fmaf(wv, B.y, acc[5]);
        acc[6] = fmaf(wv, B.z, acc[6]); acc[7] = fmaf(wv, B.w, acc[7]);
    }
}

// 3x3 conv accumulate over nch input channels, one (o,p) output row (8 q-values).
// xpad: base of channel 0 for this conv's input (padded 9x12 per channel)
// wrow: smem weights for this o, stride 9 per input channel
__device__ __forceinline__ void conv3x3_row(float acc[8], const float* __restrict__ xpad,
                                            const float* __restrict__ wrow, int nch, int p) {
    for (int i = 0; i < nch; ++i) {
        const float4* X = (const float4*)(xpad + i * 108 + p * 12);
        float4 a0 = X[0], a1 = X[1], a2 = X[2];
        float4 b0 = X[3], b1 = X[4], b2 = X[5];
        float4 c0 = X[6], c1 = X[7], c2 = X[8];
        float x0[12] = {a0.x,a0.y,a0.z,a0.w,a1.x,a1.y,a1.z,a1.w,a2.x,a2.y,a2.z,a2.w};
        float x1[12] = {b0.x,b0.y,b0.z,b0.w,b1.x,b1.y,b1.z,b1.w,b2.x,b2.y,b2.z,b2.w};
        float x2[12] = {c0.x,c0.y,c0.z,c0.w,c1.x,c1.y,c1.z,c1.w,c2.x,c2.y,c2.z,c2.w};
        const float* w = wrow + i * 9;
        float w0=w[0],w1=w[1],w2=w[2],w3=w[3],w4=w[4],w5=w[5],w6=w[6],w7=w[7],w8=w[8];
        #pragma unroll
        for (int q = 0; q < 8; ++q) {
            float s = fmaf(w0, x0[q],   fmaf(w1, x0[q+1], fmaf(w2, x0[q+2],
                      fmaf(w3, x1[q],   fmaf(w4, x1[q+1], fmaf(w5, x1[q+2],
                      fmaf(w6, x2[q],   fmaf(w7, x2[q+1],      w8 * x2[q+2]))))))));
            acc[q] += s;
        }
    }
}

__global__ void __launch_bounds__(256) occ_fused_kernel(
    const float* __restrict__ mg,
    const float* __restrict__ w_cr, const float* __restrict__ b_cr,
    const float* __restrict__ bnr_w, const float* __restrict__ bnr_b,
    const float* __restrict__ bnr_m, const float* __restrict__ bnr_v,
    const float* __restrict__ q_w,  const float* __restrict__ q_b,
    const float* __restrict__ k_w,  const float* __restrict__ k_b,
    const float* __restrict__ v_w,  const float* __restrict__ v_b,
    const float* __restrict__ gamma,
    const float* __restrict__ ln_w, const float* __restrict__ ln_b,
    const float* __restrict__ w_res, const float* __restrict__ b_res,
    const float* __restrict__ bnres_w, const float* __restrict__ bnres_b,
    const float* __restrict__ bnres_m, const float* __restrict__ bnres_v,
    const float* __restrict__ w1,  const float* __restrict__ b1,
    const float* __restrict__ bn1_w, const float* __restrict__ bn1_b,
    const float* __restrict__ bn1_m, const float* __restrict__ bn1_v,
    const float* __restrict__ w2,  const float* __restrict__ b2,
    float* __restrict__ out)
{
    extern __shared__ float sm[];
    const int t = threadIdx.x;
    const int b = blockIdx.x;

    float* pooled = sm + R1_OFF;
    float* xbuf   = sm + R2_OFF;
    float* ws     = sm + WS_OFF;
    float* red    = sm + RED_OFF;

    // ============ Stage A: adaptive avg pool 16x16 -> 7x8, plus weight staging ============
    {
        const float* in = mg + (size_t)b * 32768;   // 128*16*16
        for (int idx = t; idx < 7168; idx += 256) {
            int c = idx / 56, s = idx - c * 56, p = s >> 3, q = s & 7;
            int r0 = (p * 16) / 7;
            int r1 = ((p + 1) * 16 + 6) / 7;
            const float2* bp = (const float2*)(in + c * 256 + q * 2);
            float acc = 0.f;
            for (int r = r0; r < r1; ++r) { float2 v2 = bp[r * 8]; acc += v2.x + v2.y; }
            pooled[idx] = acc * (0.5f / (float)(r1 - r0));
        }
        for (int idx = t; idx < 4096; idx += 256) {
            int o = idx >> 7, c = idx & 127;
            sm[WCR_OFF + o * 129 + c] = w_cr[idx];
        }
        for (int idx = t; idx < 128; idx += 256) {
            int d = idx >> 5, o = idx & 31;
            sm[QW_OFF + d * 33 + o] = q_w[idx];
            sm[KW_OFF + d * 33 + o] = k_w[idx];
        }
        for (int idx = t; idx < 1024; idx += 256) {
            int c = idx >> 5, o = idx & 31;
            sm[VW_OFF + c * 33 + o] = v_w[idx];
        }
    }
    __syncthreads();

    // ============ Stage B: 1x1 channel reduce 128->32 + BN + ReLU -> xbuf[32][56] ============
    if (t < 224) {
        int o = t / 7, p = t % 7;
        float acc[8] = {0,0,0,0,0,0,0,0};
        gemm_row8(acc, sm + WCR_OFF + o * 129, 1, pooled + p * 8, 56, 128);
        float sc = bnr_w[o] * rsqrtf(bnr_v[o] + EPSV);
        float bi = b_cr[o] * sc + bnr_b[o] - bnr_m[o] * sc;
        float* xo = xbuf + o * 56 + p * 8;
        #pragma unroll
        for (int q = 0; q < 8; ++q) xo[q] = fmaxf(fmaf(acc[q], sc, bi), 0.f);
    }
    __syncthreads();

    // ============ Stage C1: q,k,v projections ============
    for (int u = t; u < 280; u += 256) {
        if (u < 224) {
            int c = u / 7, p = u % 7;
            float bias = v_b[c];
            float acc[8] = {bias,bias,bias,bias,bias,bias,bias,bias};
            gemm_row8(acc, sm + VW_OFF + c * 33, 1, xbuf + p * 8, 56, 32);
            float* vo = sm + V_OFF + c * 56 + p * 8;
            #pragma unroll
            for (int q = 0; q < 8; ++q) vo[q] = acc[q];
        } else {
            int u2 = u - 224;
            int dk = u2 / 7, p = u2 % 7;
            int d = dk & 3;
            const float* wp = sm + (dk < 4 ? QW_OFF : KW_OFF) + d * 33;
            float bias = (dk < 4) ? q_b[d] : k_b[d];
            float acc[8] = {bias,bias,bias,bias,bias,bias,bias,bias};
            gemm_row8(acc, wp, 1, xbuf + p * 8, 56, 32);
            float* dst = sm + (dk < 4 ? Q_OFF : K_OFF) + d * 56 + p * 8;
            #pragma unroll
            for (int q = 0; q < 8; ++q) dst[q] = acc[q];
        }
    }
    __syncthreads();

    // ============ Stage C2: scores S[i][j] = sum_d q[d][i]*k[d][j] ============
    for (int u = t; u < 392; u += 256) {
        int i = u / 7, pj = u % 7;
        float acc[8] = {0,0,0,0,0,0,0,0};
        gemm_row8(acc, sm + Q_OFF + i, 56, sm + K_OFF + pj * 8, 56, 4);
        float* arow = sm + ATT_OFF + i * 57 + pj * 8;
        #pragma unroll
        for (int q = 0; q < 8; ++q) arow[q] = acc[q];
    }
    __syncthreads();

    // ============ softmax over j per row i ============
    if (t < 56) {
        float* row = sm + ATT_OFF + t * 57;
        float m = -1e30f;
        for (int j = 0; j < 56; ++j) m = fmaxf(m, row[j]);
        float ssum = 0.f;
        for (int j = 0; j < 56; ++j) { float e = __expf(row[j] - m); row[j] = e; ssum += e; }
        float inv = 1.f / ssum;
        for (int j = 0; j < 56; ++j) row[j] *= inv;
    }
    __syncthreads();

    // ============ Stage C3: out[c][i] = sum_j v[c][j]*attn[i][j]; x = gamma*out + x ============
    {
        float g = gamma[0];
        if (t < 224) {
            int c = t / 7, pi = t % 7;
            float acc[8] = {0,0,0,0,0,0,0,0};
            const float* vr = sm + V_OFF + c * 56;
            const float* ar = sm + ATT_OFF + pi * 8 * 57;
            for (int j = 0; j < 56; ++j) {
                float vv = vr[j];
                #pragma unroll
                for (int ii = 0; ii < 8; ++ii)
                    acc[ii] = fmaf(vv, ar[ii * 57 + j], acc[ii]);
            }
            float* xo = xbuf + c * 56 + pi * 8;
            #pragma unroll
            for (int ii = 0; ii < 8; ++ii) xo[ii] = fmaf(g, acc[ii], xo[ii]);
        }
    }
    __syncthreads();

    // ============ Stage D: LayerNorm over 32*7*8=1792, write padded xpadA ============
    float* xpadA = sm + R1_OFF;
    float* xpadB = sm + R2_OFF;
    {
        float s1 = 0.f, s2 = 0.f;
        #pragma unroll
        for (int k2 = 0; k2 < 7; ++k2) {
            float v = xbuf[t + k2 * 256];
            s1 += v; s2 = fmaf(v, v, s2);
        }
        #pragma unroll
        for (int off = 16; off; off >>= 1) {
            s1 += __shfl_xor_sync(0xffffffffu, s1, off);
            s2 += __shfl_xor_sync(0xffffffffu, s2, off);
        }
        if ((t & 31) == 0) { red[t >> 5] = s1; red[8 + (t >> 5)] = s2; }
        __syncthreads();
        if (t == 0) {
            float S1 = 0.f, S2 = 0.f;
            for (int w = 0; w < 8; ++w) { S1 += red[w]; S2 += red[8 + w]; }
            float mu = S1 * (1.f / 1792.f);
            float var = S2 * (1.f / 1792.f) - mu * mu;
            red[16] = mu;
            red[17] = rsqrtf(var + EPSV);
        }
        __syncthreads();
        float mu = red[16], inv = red[17];
        float vals[7];
        #pragma unroll
        for (int k2 = 0; k2 < 7; ++k2) {
            int idx = t + k2 * 256;
            vals[k2] = (xbuf[idx] - mu) * inv * ln_w[idx] + ln_b[idx];
        }
        __syncthreads();   // all xbuf reads done before zeroing xpadB over it
        for (int idx = t; idx < 3456; idx += 256) { xpadA[idx] = 0.f; xpadB[idx] = 0.f; }
        // stage w_res first half (input channels 0..15) while zeroing
        for (int idx = t; idx < 4608; idx += 256) {
            int o = idx / 144, r = idx - o * 144;
            ws[o * 145 + r] = w_res[o * 288 + r];
        }
        __syncthreads();
        #pragma unroll
        for (int k2 = 0; k2 < 7; ++k2) {
            int idx = t + k2 * 256;
            int c = idx / 56, s = idx - c * 56, p = s >> 3, q = s & 7;
            xpadA[c * 108 + (p + 1) * 12 + (q + 1)] = vals[k2];
        }
    }
    __syncthreads();

    // ============ Stage E: residual 3x3 conv 32->32 + BN + ReLU + residual -> xpadB ============
    {
        int o = 0, p = 0;
        bool act = (t < 224);
        if (act) { o = t / 7; p = t % 7; }
        float acc[8] = {0,0,0,0,0,0,0,0};
        if (act) conv3x3_row(acc, xpadA, ws + o * 145, 16, p);          // channels 0..15
        __syncthreads();
        for (int idx = t; idx < 4608; idx += 256) {                      // second half weights
            int oo = idx / 144, r = idx - oo * 144;
            ws[oo * 145 + r] = w_res[oo * 288 + 144 + r];
        }
        __syncthreads();
        if (act) {
            conv3x3_row(acc, xpadA + 16 * 108, ws + o * 145, 16, p);    // channels 16..31
            float sc = bnres_w[o] * rsqrtf(bnres_v[o] + EPSV);
            float bi = b_res[o] * sc + bnres_b[o] - bnres_m[o] * sc;
            float* dst = xpadB + o * 108 + (p + 1) * 12 + 1;
            const float* rsd = xpadA + o * 108 + (p + 1) * 12 + 1;
            #pragma unroll
            for (int q = 0; q < 8; ++q)
                dst[q] = fmaxf(fmaf(acc[q], sc, bi), 0.f) + rsd[q];
        }
    }
    __syncthreads();

    // ============ stage w1 (16x32x3x3) and w2 (1x16x3x3) ============
    for (int idx = t; idx < 4608; idx += 256) {
        int o = idx / 288, r = idx - o * 288;
        ws[o * 289 + r] = w1[idx];
    }
    for (int idx = t; idx < 144; idx += 256) ws[4624 + idx] = w2[idx];
    __syncthreads();

    // ============ Stage F: conv1 3x3 32->16 + BN + ReLU -> xpadA channels 0..15 ============
    if (t < 112) {
        int o = t / 7, p = t % 7;
        float acc[8] = {0,0,0,0,0,0,0,0};
        conv3x3_row(acc, xpadB, ws + o * 289, 32, p);
        float sc = bn1_w[o] * rsqrtf(bn1_v[o] + EPSV);
        float bi = b1[o] * sc + bn1_b[o] - bn1_m[o] * sc;
        float* dst = xpadA + o * 108 + (p + 1) * 12 + 1;
        #pragma unroll
        for (int q = 0; q < 8; ++q) dst[q] = fmaxf(fmaf(acc[q], sc, bi), 0.f);
    }
    __syncthreads();

    // ============ Stage G: conv2 3x3 16->1 -> out ============
    if (t < 56) {
        int p = t >> 3, q = t & 7;
        float acc2 = b2[0];
        const float* wk = ws + 4624;
        for (int i = 0; i < 16; ++i) {
            const float* xc = xpadA + i * 108 + p * 12 + q;
            const float* w = wk + i * 9;
            acc2 = fmaf(w[0], xc[0],  acc2);
            acc2 = fmaf(w[1], xc[1],  acc2);
            acc2 = fmaf(w[2], xc[2],  acc2);
            acc2 = fmaf(w[3], xc[12], acc2);
            acc2 = fmaf(w[4], xc[13], acc2);
            acc2 = fmaf(w[5], xc[14], acc2);
            acc2 = fmaf(w[6], xc[24], acc2);
            acc2 = fmaf(w[7], xc[25], acc2);
            acc2 = fmaf(w[8], xc[26], acc2);
        }
        out[(size_t)b * 56 + t] = acc2;
    }
}

extern "C" void kernel_launch(void* const* d_in, const int* in_sizes, int n_in,
                              void* d_out, int out_size) {
    const float* mg      = (const float*)d_in[0];
    const float* w_cr    = (const float*)d_in[1];
    const float* b_cr    = (const float*)d_in[2];
    const float* bnr_w   = (const float*)d_in[3];
    const float* bnr_b   = (const float*)d_in[4];
    const float* bnr_m   = (const float*)d_in[5];
    const float* bnr_v   = (const float*)d_in[6];
    const float* q_w     = (const float*)d_in[7];
    const float* q_b     = (const float*)d_in[8];
    const float* k_w     = (const float*)d_in[9];
    const float* k_b     = (const float*)d_in[10];
    const float* v_w     = (const float*)d_in[11];
    const float* v_b     = (const float*)d_in[12];
    const float* gamma   = (const float*)d_in[13];
    const float* ln_w    = (const float*)d_in[14];
    const float* ln_b    = (const float*)d_in[15];
    const float* w_res   = (const float*)d_in[16];
    const float* b_res   = (const float*)d_in[17];
    const float* bnres_w = (const float*)d_in[18];
    const float* bnres_b = (const float*)d_in[19];
    const float* bnres_m = (const float*)d_in[20];
    const float* bnres_v = (const float*)d_in[21];
    const float* w1      = (const float*)d_in[22];
    const float* b1      = (const float*)d_in[23];
    const float* bn1_w   = (const float*)d_in[24];
    const float* bn1_b   = (const float*)d_in[25];
    const float* bn1_m   = (const float*)d_in[26];
    const float* bn1_v   = (const float*)d_in[27];
    const float* w2      = (const float*)d_in[28];
    const float* b2      = (const float*)d_in[29];

    int B = in_sizes[0] / 32768;   // 128*16*16 per sample
    size_t smem_bytes = SMEM_FLOATS * sizeof(float);
    cudaFuncSetAttribute(occ_fused_kernel,
                         cudaFuncAttributeMaxDynamicSharedMemorySize, (int)smem_bytes);
    occ_fused_kernel<<<B, 256, smem_bytes>>>(
        mg, w_cr, b_cr, bnr_w, bnr_b, bnr_m, bnr_v,
        q_w, q_b, k_w, k_b, v_w, v_b, gamma, ln_w, ln_b,
        w_res, b_res, bnres_w, bnres_b, bnres_m, bnres_v,
        w1, b1, bn1_w, bn1_b, bn1_m, bn1_v, w2, b2,
        (float*)d_out);
}

// round 3
// speedup vs baseline: 1.1780x; 1.1780x over previous
#include <cuda_runtime.h>

#define EPSV 1e-5f
typedef unsigned long long ull;

// ---------------- shared memory layout (float offsets) ----------------
// Region R1 [0, 7168): pooled[128][56]  ->  QT(240)+KT(240)+VT(1792)+S(56x60)
//                      -> phase2: xpadA[32][9][12] (3456)
// Region R2 [7168, 11264): wcrT[128][32] swizzled -> attnT[56][60]
//                      -> phase2: xpadB (3456)
// Region WREG [11264, 16064): vTw(1024)+qw(132)+kw(132)+xbuf[32][60](1920)
//                      -> phase2: wresT half (144x32=4608), then w1T(2x2320)+w2(144)
// RED [16064, 16096)
#define POOL_OFF 0
#define QT_OFF   0
#define KT_OFF   240
#define VT_OFF   480
#define S_OFF    2272
#define XPA_OFF  0

#define WCRT_OFF 7168
#define ATT_OFF  7168
#define XPB_OFF  7168

#define WREG_OFF 11264
#define VTW_OFF  11264
#define QW_OFF   12288
#define KW_OFF   12420
#define XBUF_OFF 12552
#define W2_OFF   (WREG_OFF + 4640)

#define RED_OFF  16064
#define SMEM_FLOATS 16096

// ---------------- packed f32x2 helpers (inline PTX; ptxas never auto-fuses) ---
__device__ __forceinline__ ull pk2(float x, float y) {
    ull r; asm("mov.b64 %0, {%1, %2};" : "=l"(r) : "f"(x), "f"(y)); return r;
}
__device__ __forceinline__ void up2(ull v, float& x, float& y) {
    asm("mov.b64 {%0, %1}, %2;" : "=f"(x), "=f"(y) : "l"(v));
}
__device__ __forceinline__ ull fma2(ull a, ull b, ull c) {
    ull r; asm("fma.rn.f32x2 %0, %1, %2, %3;" : "=l"(r) : "l"(a), "l"(b), "l"(c)); return r;
}
__device__ __forceinline__ ull add2(ull a, ull b) {
    ull r; asm("add.rn.f32x2 %0, %1, %2;" : "=l"(r) : "l"(a), "l"(b)); return r;
}

// 8-wide GEMM step: acc[4] (f32x2 pairs) += w * x[0..7], x uniform across warp
__device__ __forceinline__ void g8(ull acc[4], const float* __restrict__ x, float wv) {
    ulonglong2 A = *(const ulonglong2*)(x);
    ulonglong2 B = *(const ulonglong2*)(x + 4);
    ull wp = pk2(wv, wv);
    acc[0] = fma2(wp, A.x, acc[0]); acc[1] = fma2(wp, A.y, acc[1]);
    acc[2] = fma2(wp, B.x, acc[2]); acc[3] = fma2(wp, B.y, acc[3]);
}

// 3x3 conv over 16 input channels, one output row p (8 cols), acc[4] f32x2 pairs.
// x rows are warp-uniform (broadcast); weights coalesced per-lane via XOR swizzle.
__device__ __forceinline__ void conv16(ull acc[4], const float* __restrict__ xbase,
                                       const float* __restrict__ wb, int wstride,
                                       int wmask, int o, int p) {
    for (int ch = 0; ch < 16; ++ch) {
        const float* xr = xbase + ch * 108 + p * 12;
        #pragma unroll
        for (int r = 0; r < 3; ++r) {
            const float* row = xr + r * 12;
            ulonglong2 u01 = *(const ulonglong2*)(row);
            ulonglong2 u23 = *(const ulonglong2*)(row + 4);
            ull P4 = *(const ull*)(row + 8);
            ull P0 = u01.x, P1 = u01.y, P2 = u23.x, P3 = u23.y;
            float x0,x1,x2,x3,x4,x5,x6,x7,x8,x9;
            up2(P0,x0,x1); up2(P1,x2,x3); up2(P2,x4,x5); up2(P3,x6,x7); up2(P4,x8,x9);
            ull O0 = pk2(x1,x2), O1 = pk2(x3,x4), O2 = pk2(x5,x6), O3 = pk2(x7,x8);
            int rT = ch * 9 + r * 3;
            float wv0 = wb[(rT + 0) * wstride + (o ^ ((rT + 0) & wmask))];
            float wv1 = wb[(rT + 1) * wstride + (o ^ ((rT + 1) & wmask))];
            float wv2 = wb[(rT + 2) * wstride + (o ^ ((rT + 2) & wmask))];
            ull w0 = pk2(wv0, wv0), w1 = pk2(wv1, wv1), w2 = pk2(wv2, wv2);
            acc[0] = fma2(w0, P0, acc[0]); acc[1] = fma2(w0, P1, acc[1]);
            acc[2] = fma2(w0, P2, acc[2]); acc[3] = fma2(w0, P3, acc[3]);
            acc[0] = fma2(w1, O0, acc[0]); acc[1] = fma2(w1, O1, acc[1]);
            acc[2] = fma2(w1, O2, acc[2]); acc[3] = fma2(w1, O3, acc[3]);
            acc[0] = fma2(w2, P1, acc[0]); acc[1] = fma2(w2, P2, acc[1]);
            acc[2] = fma2(w2, P3, acc[2]); acc[3] = fma2(w2, P4, acc[3]);
        }
    }
}

__global__ void __launch_bounds__(256, 3) occ_fused_kernel(
    const float* __restrict__ mg,
    const float* __restrict__ w_cr, const float* __restrict__ b_cr,
    const float* __restrict__ bnr_w, const float* __restrict__ bnr_b,
    const float* __restrict__ bnr_m, const float* __restrict__ bnr_v,
    const float* __restrict__ q_w,  const float* __restrict__ q_b,
    const float* __restrict__ k_w,  const float* __restrict__ k_b,
    const float* __restrict__ v_w,  const float* __restrict__ v_b,
    const float* __restrict__ gamma,
    const float* __restrict__ ln_w, const float* __restrict__ ln_b,
    const float* __restrict__ w_res, const float* __restrict__ b_res,
    const float* __restrict__ bnres_w, const float* __restrict__ bnres_b,
    const float* __restrict__ bnres_m, const float* __restrict__ bnres_v,
    const float* __restrict__ w1,  const float* __restrict__ b1,
    const float* __restrict__ bn1_w, const float* __restrict__ bn1_b,
    const float* __restrict__ bn1_m, const float* __restrict__ bn1_v,
    const float* __restrict__ w2,  const float* __restrict__ b2,
    float* __restrict__ out)
{
    extern __shared__ float sm[];
    const int t = threadIdx.x;
    const int b = blockIdx.x;
    const int w = t >> 5;
    const int lane = t & 31;
    float* red = sm + RED_OFF;

    // ============ Stage A: adaptive pool 16x16 -> 7x8 + stage phase-1 weights ======
    {
        const float* in = mg + (size_t)b * 32768;
        for (int idx = t; idx < 7168; idx += 256) {
            int c = idx / 56, s = idx - c * 56, p = s >> 3, q = s & 7;
            int r0 = (p * 16) / 7;
            int r1 = ((p + 1) * 16 + 6) / 7;
            const float2* bp = (const float2*)(in + c * 256 + q * 2);
            float acc = 0.f;
            for (int r = r0; r < r1; ++r) { float2 v2 = bp[r * 8]; acc += v2.x + v2.y; }
            sm[POOL_OFF + idx] = acc * (0.5f / (float)(r1 - r0));
        }
        for (int idx = t; idx < 4096; idx += 256) {       // wcrT[c][o] XOR-swizzled
            int o = idx >> 7, c = idx & 127;
            sm[WCRT_OFF + c * 32 + (o ^ (c & 31))] = w_cr[idx];
        }
        for (int idx = t; idx < 1024; idx += 256) {       // vTw[in][out] swizzled
            int o = idx >> 5, in2 = idx & 31;
            sm[VTW_OFF + in2 * 32 + (o ^ (in2 & 31))] = v_w[idx];
        }
        if (t < 128) {
            int d = t >> 5, in2 = t & 31;
            sm[QW_OFF + d * 33 + in2] = q_w[t];
            sm[KW_OFF + d * 33 + in2] = k_w[t];
        }
    }
    __syncthreads();

    // ============ Stage B: 1x1 128->32 + BN + ReLU. warp=p, lane=o ============
    if (w < 7) {
        ull a[4] = {0,0,0,0};
        const float* xb = sm + POOL_OFF + w * 8;
        #pragma unroll 4
        for (int c = 0; c < 128; ++c) {
            float wv = sm[WCRT_OFF + c * 32 + (lane ^ (c & 31))];
            g8(a, xb + c * 56, wv);
        }
        float sc = bnr_w[lane] * rsqrtf(bnr_v[lane] + EPSV);
        float bi = fmaf(b_cr[lane], sc, bnr_b[lane] - bnr_m[lane] * sc);
        float r[8];
        up2(a[0],r[0],r[1]); up2(a[1],r[2],r[3]); up2(a[2],r[4],r[5]); up2(a[3],r[6],r[7]);
        float* dst = sm + XBUF_OFF + lane * 60 + w * 8;
        #pragma unroll
        for (int q = 0; q < 8; ++q) dst[q] = fmaxf(fmaf(r[q], sc, bi), 0.f);
    }
    __syncthreads();

    // ============ Stage C1: v (warps 0-6), q & k (warp 7) ============
    if (w < 7) {
        float bias = v_b[lane];
        ull a[4]; a[0]=a[1]=a[2]=a[3]=pk2(bias,bias);
        const float* xb = sm + XBUF_OFF + w * 8;
        #pragma unroll 4
        for (int in2 = 0; in2 < 32; ++in2) {
            float wv = sm[VTW_OFF + in2 * 32 + (lane ^ (in2 & 31))];
            g8(a, xb + in2 * 60, wv);
        }
        float r[8];
        up2(a[0],r[0],r[1]); up2(a[1],r[2],r[3]); up2(a[2],r[4],r[5]); up2(a[3],r[6],r[7]);
        #pragma unroll
        for (int q = 0; q < 8; ++q) sm[VT_OFF + (w * 8 + q) * 32 + lane] = r[q];
    } else if (lane < 28) {
        int d = lane / 7, p = lane - d * 7;
        const float* xb = sm + XBUF_OFF + p * 8;
        #pragma unroll
        for (int pass = 0; pass < 2; ++pass) {
            const float* W = sm + (pass ? KW_OFF : QW_OFF) + d * 33;
            float bias = pass ? k_b[d] : q_b[d];
            ull a[4]; a[0]=a[1]=a[2]=a[3]=pk2(bias,bias);
            for (int in2 = 0; in2 < 32; ++in2) g8(a, xb + in2 * 60, W[in2]);
            float r[8];
            up2(a[0],r[0],r[1]); up2(a[1],r[2],r[3]); up2(a[2],r[4],r[5]); up2(a[3],r[6],r[7]);
            float* dst = sm + (pass ? KT_OFF : QT_OFF) + d * 60 + p * 8;
            #pragma unroll
            for (int q = 0; q < 8; ++q) dst[q] = r[q];
        }
    }
    __syncthreads();

    // ============ Stage C2: S[i][j] = sum_d q[d][i] k[d][j]. warp=i-octet, lane=j ==
    if (w < 7) {
        int i0 = w * 8;
        #pragma unroll
        for (int seg = 0; seg < 2; ++seg) {
            int j = seg * 32 + lane;
            if (j < 56) {
                ull a[4] = {0,0,0,0};
                #pragma unroll
                for (int d = 0; d < 4; ++d) {
                    float kv = sm[KT_OFF + d * 60 + j];
                    g8(a, sm + QT_OFF + d * 60 + i0, kv);
                }
                float r[8];
                up2(a[0],r[0],r[1]); up2(a[1],r[2],r[3]); up2(a[2],r[4],r[5]); up2(a[3],r[6],r[7]);
                #pragma unroll
                for (int q = 0; q < 8; ++q) sm[S_OFF + (i0 + q) * 60 + j] = r[q];
            }
        }
    }
    __syncthreads();

    // ============ softmax rows, write transposed attnT[j][i] ============
    if (t < 56) {
        float* row = sm + S_OFF + t * 60;
        const float4* r4 = (const float4*)row;
        float m = -1e30f;
        #pragma unroll
        for (int k = 0; k < 14; ++k) {
            float4 vv = r4[k];
            m = fmaxf(m, fmaxf(fmaxf(vv.x, vv.y), fmaxf(vv.z, vv.w)));
        }
        float ssum = 0.f;
        #pragma unroll 8
        for (int j = 0; j < 56; ++j) { float e = __expf(row[j] - m); row[j] = e; ssum += e; }
        float inv = 1.f / ssum;
        #pragma unroll 8
        for (int j = 0; j < 56; ++j) sm[ATT_OFF + j * 60 + t] = row[j] * inv;
    }
    __syncthreads();

    // ============ Stage C3: out[c][i] = sum_j v[j][c]*attnT[j][i]; x += gamma*out ==
    if (w < 7) {
        int i0 = w * 8;
        ull a[4] = {0,0,0,0};
        #pragma unroll 4
        for (int j = 0; j < 56; ++j) {
            float vv = sm[VT_OFF + j * 32 + lane];
            g8(a, sm + ATT_OFF + j * 60 + i0, vv);
        }
        float r[8];
        up2(a[0],r[0],r[1]); up2(a[1],r[2],r[3]); up2(a[2],r[4],r[5]); up2(a[3],r[6],r[7]);
        float g = gamma[0];
        float* xr = sm + XBUF_OFF + lane * 60 + i0;
        #pragma unroll
        for (int q = 0; q < 8; ++q) xr[q] = fmaf(g, r[q], xr[q]);
    }
    __syncthreads();

    // ============ Stage D: LayerNorm over 1792 ============
    float vals[7];
    {
        float s1 = 0.f, s2 = 0.f;
        #pragma unroll
        for (int k = 0; k < 7; ++k) {
            int v = t + k * 256;
            int c = v / 56, s = v - c * 56;
            float x = sm[XBUF_OFF + c * 60 + s];
            vals[k] = x; s1 += x; s2 = fmaf(x, x, s2);
        }
        #pragma unroll
        for (int off = 16; off; off >>= 1) {
            s1 += __shfl_xor_sync(0xffffffffu, s1, off);
            s2 += __shfl_xor_sync(0xffffffffu, s2, off);
        }
        if (lane == 0) { red[w] = s1; red[8 + w] = s2; }
        __syncthreads();
        if (t == 0) {
            float S1 = 0.f, S2 = 0.f;
            for (int k = 0; k < 8; ++k) { S1 += red[k]; S2 += red[8 + k]; }
            float mu = S1 * (1.f / 1792.f);
            float var = S2 * (1.f / 1792.f) - mu * mu;
            red[16] = mu; red[17] = rsqrtf(var + EPSV);
        }
        __syncthreads();
        float mu = red[16], inv = red[17];
        #pragma unroll
        for (int k = 0; k < 7; ++k) {
            int v = t + k * 256;
            vals[k] = (vals[k] - mu) * inv * ln_w[v] + ln_b[v];
        }
    }
    __syncthreads();   // all xbuf/attn reads done; regions reusable

    // zero pads of xpadA/xpadB; stage w_res half 1 (in-ch 0..15)
    for (int idx = t; idx < 6912; idx += 256) {
        float* base = (idx < 3456) ? (sm + XPA_OFF) : (sm + XPB_OFF - 3456);
        base[idx] = 0.f;
    }
    for (int idx = t; idx < 4608; idx += 256) {
        int o = idx / 144, r = idx - o * 144;
        sm[WREG_OFF + r * 32 + (o ^ (r & 31))] = w_res[o * 288 + r];
    }
    __syncthreads();
    #pragma unroll
    for (int k = 0; k < 7; ++k) {   // scatter LN output into padded xpadA
        int v = t + k * 256;
        int c = v / 56, s = v - c * 56, p = s >> 3, q = s & 7;
        sm[XPA_OFF + c * 108 + (p + 1) * 12 + (q + 1)] = vals[k];
    }
    __syncthreads();

    // ============ Stage E: residual 3x3 conv 32->32 (+BN+ReLU+res). warp=p, lane=o =
    ull e[4] = {0,0,0,0};
    if (w < 7) conv16(e, sm + XPA_OFF, sm + WREG_OFF, 32, 31, lane, w);
    __syncthreads();
    for (int idx = t; idx < 4608; idx += 256) {    // stage w_res half 2
        int o = idx / 144, r = idx - o * 144;
        sm[WREG_OFF + r * 32 + (o ^ (r & 31))] = w_res[o * 288 + 144 + r];
    }
    __syncthreads();
    if (w < 7) {
        conv16(e, sm + XPA_OFF + 16 * 108, sm + WREG_OFF, 32, 31, lane, w);
        float sc = bnres_w[lane] * rsqrtf(bnres_v[lane] + EPSV);
        float bi = fmaf(b_res[lane], sc, bnres_b[lane] - bnres_m[lane] * sc);
        float r[8];
        up2(e[0],r[0],r[1]); up2(e[1],r[2],r[3]); up2(e[2],r[4],r[5]); up2(e[3],r[6],r[7]);
        const float* rs = sm + XPA_OFF + lane * 108 + (w + 1) * 12 + 1;
        float* db = sm + XPB_OFF + lane * 108 + (w + 1) * 12 + 1;
        #pragma unroll
        for (int q = 0; q < 8; ++q)
            db[q] = fmaxf(fmaf(r[q], sc, bi), 0.f) + rs[q];
    }
    __syncthreads();

    // stage w1T (two half-blocks, 16-wide, offset 2320 apart) + w2
    for (int idx = t; idx < 4608; idx += 256) {
        int o = idx / 288, rr = idx - o * 288;
        int half = rr / 144, rp = rr - half * 144;
        sm[WREG_OFF + half * 2320 + rp * 16 + (o ^ (rp & 15))] = w1[idx];
    }
    if (t < 144) sm[W2_OFF + t] = w2[t];
    __syncthreads();

    // ============ Stage F: conv1 3x3 32->16 + BN + ReLU. lane halves split in-ch ===
    if (w < 7) {
        int o16 = lane & 15, half = lane >> 4;
        ull f[4] = {0,0,0,0};
        conv16(f, sm + XPB_OFF + half * 1728, sm + WREG_OFF + half * 2320, 16, 15, o16, w);
        #pragma unroll
        for (int m = 0; m < 4; ++m) {
            ull other = __shfl_xor_sync(0xffffffffu, f[m], 16);
            f[m] = add2(f[m], other);
        }
        if (half == 0) {
            float sc = bn1_w[o16] * rsqrtf(bn1_v[o16] + EPSV);
            float bi = fmaf(b1[o16], sc, bn1_b[o16] - bn1_m[o16] * sc);
            float r[8];
            up2(f[0],r[0],r[1]); up2(f[1],r[2],r[3]); up2(f[2],r[4],r[5]); up2(f[3],r[6],r[7]);
            float* dst = sm + XPA_OFF + o16 * 108 + (w + 1) * 12 + 1;
            #pragma unroll
            for (int q = 0; q < 8; ++q) dst[q] = fmaxf(fmaf(r[q], sc, bi), 0.f);
        }
    }
    __syncthreads();

    // ============ Stage G: conv2 3x3 16->1 ============
    if (t < 56) {
        int p = t >> 3, q = t & 7;
        float acc2 = b2[0];
        #pragma unroll 4
        for (int i = 0; i < 16; ++i) {
            const float* xc = sm + XPA_OFF + i * 108 + p * 12 + q;
            const float* wg = sm + W2_OFF + i * 9;
            acc2 = fmaf(wg[0], xc[0],  acc2);
            acc2 = fmaf(wg[1], xc[1],  acc2);
            acc2 = fmaf(wg[2], xc[2],  acc2);
            acc2 = fmaf(wg[3], xc[12], acc2);
            acc2 = fmaf(wg[4], xc[13], acc2);
            acc2 = fmaf(wg[5], xc[14], acc2);
            acc2 = fmaf(wg[6], xc[24], acc2);
            acc2 = fmaf(wg[7], xc[25], acc2);
            acc2 = fmaf(wg[8], xc[26], acc2);
        }
        out[(size_t)b * 56 + t] = acc2;
    }
}

extern "C" void kernel_launch(void* const* d_in, const int* in_sizes, int n_in,
                              void* d_out, int out_size) {
    const float* mg      = (const float*)d_in[0];
    const float* w_cr    = (const float*)d_in[1];
    const float* b_cr    = (const float*)d_in[2];
    const float* bnr_w   = (const float*)d_in[3];
    const float* bnr_b   = (const float*)d_in[4];
    const float* bnr_m   = (const float*)d_in[5];
    const float* bnr_v   = (const float*)d_in[6];
    const float* q_w     = (const float*)d_in[7];
    const float* q_b     = (const float*)d_in[8];
    const float* k_w     = (const float*)d_in[9];
    const float* k_b     = (const float*)d_in[10];
    const float* v_w     = (const float*)d_in[11];
    const float* v_b     = (const float*)d_in[12];
    const float* gamma   = (const float*)d_in[13];
    const float* ln_w    = (const float*)d_in[14];
    const float* ln_b    = (const float*)d_in[15];
    const float* w_res   = (const float*)d_in[16];
    const float* b_res   = (const float*)d_in[17];
    const float* bnres_w = (const float*)d_in[18];
    const float* bnres_b = (const float*)d_in[19];
    const float* bnres_m = (const float*)d_in[20];
    const float* bnres_v = (const float*)d_in[21];
    const float* w1      = (const float*)d_in[22];
    const float* b1      = (const float*)d_in[23];
    const float* bn1_w   = (const float*)d_in[24];
    const float* bn1_b   = (const float*)d_in[25];
    const float* bn1_m   = (const float*)d_in[26];
    const float* bn1_v   = (const float*)d_in[27];
    const float* w2      = (const float*)d_in[28];
    const float* b2      = (const float*)d_in[29];

    int B = in_sizes[0] / 32768;
    size_t smem_bytes = SMEM_FLOATS * sizeof(float);
    cudaFuncSetAttribute(occ_fused_kernel,
                         cudaFuncAttributeMaxDynamicSharedMemorySize, (int)smem_bytes);
    occ_fused_kernel<<<B, 256, smem_bytes>>>(
        mg, w_cr, b_cr, bnr_w, bnr_b, bnr_m, bnr_v,
        q_w, q_b, k_w, k_b, v_w, v_b, gamma, ln_w, ln_b,
        w_res, b_res, bnres_w, bnres_b, bnres_m, bnres_v,
        w1, b1, bn1_w, bn1_b, bn1_m, bn1_v, w2, b2,
        (float*)d_out);
}

// round 4
// speedup vs baseline: 1.1787x; 1.0006x over previous
#include <cuda_runtime.h>

#define EPSV 1e-5f
typedef unsigned long long ull;

// ---------------- shared memory layout (float offsets) ----------------
// Region R1 [0, 7168): pooled[128][56]  ->  QT(240)+KT(240)+VT(1792)+S(56x60)
//                      -> phase2: xpadA[32][9][12] (3456)
// Region R2 [7168, 11264): wcrT[128][32] swizzled -> attnT[56][60]
//                      -> phase2: xpadB (3456)
// Region WREG [11264, 16064): vTw(1024)+qw(132)+kw(132)+xbuf[32][60](1920)
//                      -> phase2: wresT half (144x32=4608), then w1T(2x2320)+w2(144)
// RED [16064, 16096)
#define POOL_OFF 0
#define QT_OFF   0
#define KT_OFF   240
#define VT_OFF   480
#define S_OFF    2272
#define XPA_OFF  0

#define WCRT_OFF 7168
#define ATT_OFF  7168
#define XPB_OFF  7168

#define WREG_OFF 11264
#define VTW_OFF  11264
#define QW_OFF   12288
#define KW_OFF   12420
#define XBUF_OFF 12552
#define W2_OFF   (WREG_OFF + 4640)

#define RED_OFF  16064
#define SMEM_FLOATS 16096

// ---------------- packed f32x2 helpers (inline PTX; ptxas never auto-fuses) ---
__device__ __forceinline__ ull pk2(float x, float y) {
    ull r; asm("mov.b64 %0, {%1, %2};" : "=l"(r) : "f"(x), "f"(y)); return r;
}
__device__ __forceinline__ void up2(ull v, float& x, float& y) {
    asm("mov.b64 {%0, %1}, %2;" : "=f"(x), "=f"(y) : "l"(v));
}
__device__ __forceinline__ ull fma2(ull a, ull b, ull c) {
    ull r; asm("fma.rn.f32x2 %0, %1, %2, %3;" : "=l"(r) : "l"(a), "l"(b), "l"(c)); return r;
}
__device__ __forceinline__ ull add2(ull a, ull b) {
    ull r; asm("add.rn.f32x2 %0, %1, %2;" : "=l"(r) : "l"(a), "l"(b)); return r;
}

// 8-wide GEMM step: acc[4] (f32x2 pairs) += w * x[0..7], x uniform across warp
__device__ __forceinline__ void g8(ull acc[4], const float* __restrict__ x, float wv) {
    ulonglong2 A = *(const ulonglong2*)(x);
    ulonglong2 B = *(const ulonglong2*)(x + 4);
    ull wp = pk2(wv, wv);
    acc[0] = fma2(wp, A.x, acc[0]); acc[1] = fma2(wp, A.y, acc[1]);
    acc[2] = fma2(wp, B.x, acc[2]); acc[3] = fma2(wp, B.y, acc[3]);
}

// 3x3 conv over 16 input channels, one output row p (8 cols), acc[4] f32x2 pairs.
// x rows are warp-uniform (broadcast); weights coalesced per-lane via XOR swizzle.
__device__ __forceinline__ void conv16(ull acc[4], const float* __restrict__ xbase,
                                       const float* __restrict__ wb, int wstride,
                                       int wmask, int o, int p) {
    for (int ch = 0; ch < 16; ++ch) {
        const float* xr = xbase + ch * 108 + p * 12;
        #pragma unroll
        for (int r = 0; r < 3; ++r) {
            const float* row = xr + r * 12;
            ulonglong2 u01 = *(const ulonglong2*)(row);
            ulonglong2 u23 = *(const ulonglong2*)(row + 4);
            ull P4 = *(const ull*)(row + 8);
            ull P0 = u01.x, P1 = u01.y, P2 = u23.x, P3 = u23.y;
            float x0,x1,x2,x3,x4,x5,x6,x7,x8,x9;
            up2(P0,x0,x1); up2(P1,x2,x3); up2(P2,x4,x5); up2(P3,x6,x7); up2(P4,x8,x9);
            ull O0 = pk2(x1,x2), O1 = pk2(x3,x4), O2 = pk2(x5,x6), O3 = pk2(x7,x8);
            int rT = ch * 9 + r * 3;
            float wv0 = wb[(rT + 0) * wstride + (o ^ ((rT + 0) & wmask))];
            float wv1 = wb[(rT + 1) * wstride + (o ^ ((rT + 1) & wmask))];
            float wv2 = wb[(rT + 2) * wstride + (o ^ ((rT + 2) & wmask))];
            ull w0 = pk2(wv0, wv0), w1 = pk2(wv1, wv1), w2 = pk2(wv2, wv2);
            acc[0] = fma2(w0, P0, acc[0]); acc[1] = fma2(w0, P1, acc[1]);
            acc[2] = fma2(w0, P2, acc[2]); acc[3] = fma2(w0, P3, acc[3]);
            acc[0] = fma2(w1, O0, acc[0]); acc[1] = fma2(w1, O1, acc[1]);
            acc[2] = fma2(w1, O2, acc[2]); acc[3] = fma2(w1, O3, acc[3]);
            acc[0] = fma2(w2, P1, acc[0]); acc[1] = fma2(w2, P2, acc[1]);
            acc[2] = fma2(w2, P3, acc[2]); acc[3] = fma2(w2, P4, acc[3]);
        }
    }
}

__global__ void __launch_bounds__(256, 3) occ_fused_kernel(
    const float* __restrict__ mg,
    const float* __restrict__ w_cr, const float* __restrict__ b_cr,
    const float* __restrict__ bnr_w, const float* __restrict__ bnr_b,
    const float* __restrict__ bnr_m, const float* __restrict__ bnr_v,
    const float* __restrict__ q_w,  const float* __restrict__ q_b,
    const float* __restrict__ k_w,  const float* __restrict__ k_b,
    const float* __restrict__ v_w,  const float* __restrict__ v_b,
    const float* __restrict__ gamma,
    const float* __restrict__ ln_w, const float* __restrict__ ln_b,
    const float* __restrict__ w_res, const float* __restrict__ b_res,
    const float* __restrict__ bnres_w, const float* __restrict__ bnres_b,
    const float* __restrict__ bnres_m, const float* __restrict__ bnres_v,
    const float* __restrict__ w1,  const float* __restrict__ b1,
    const float* __restrict__ bn1_w, const float* __restrict__ bn1_b,
    const float* __restrict__ bn1_m, const float* __restrict__ bn1_v,
    const float* __restrict__ w2,  const float* __restrict__ b2,
    float* __restrict__ out)
{
    extern __shared__ float sm[];
    const int t = threadIdx.x;
    const int b = blockIdx.x;
    const int w = t >> 5;
    const int lane = t & 31;
    float* red = sm + RED_OFF;

    // ============ Stage A: adaptive pool 16x16 -> 7x8 + stage phase-1 weights ======
    {
        const float* in = mg + (size_t)b * 32768;
        for (int idx = t; idx < 7168; idx += 256) {
            int c = idx / 56, s = idx - c * 56, p = s >> 3, q = s & 7;
            int r0 = (p * 16) / 7;
            int r1 = ((p + 1) * 16 + 6) / 7;
            const float2* bp = (const float2*)(in + c * 256 + q * 2);
            float acc = 0.f;
            for (int r = r0; r < r1; ++r) { float2 v2 = bp[r * 8]; acc += v2.x + v2.y; }
            sm[POOL_OFF + idx] = acc * (0.5f / (float)(r1 - r0));
        }
        for (int idx = t; idx < 4096; idx += 256) {       // wcrT[c][o] XOR-swizzled
            int o = idx >> 7, c = idx & 127;
            sm[WCRT_OFF + c * 32 + (o ^ (c & 31))] = w_cr[idx];
        }
        for (int idx = t; idx < 1024; idx += 256) {       // vTw[in][out] swizzled
            int o = idx >> 5, in2 = idx & 31;
            sm[VTW_OFF + in2 * 32 + (o ^ (in2 & 31))] = v_w[idx];
        }
        if (t < 128) {
            int d = t >> 5, in2 = t & 31;
            sm[QW_OFF + d * 33 + in2] = q_w[t];
            sm[KW_OFF + d * 33 + in2] = k_w[t];
        }
    }
    __syncthreads();

    // ============ Stage B: 1x1 128->32 + BN + ReLU. warp=p, lane=o ============
    if (w < 7) {
        ull a[4] = {0,0,0,0};
        const float* xb = sm + POOL_OFF + w * 8;
        #pragma unroll 4
        for (int c = 0; c < 128; ++c) {
            float wv = sm[WCRT_OFF + c * 32 + (lane ^ (c & 31))];
            g8(a, xb + c * 56, wv);
        }
        float sc = bnr_w[lane] * rsqrtf(bnr_v[lane] + EPSV);
        float bi = fmaf(b_cr[lane], sc, bnr_b[lane] - bnr_m[lane] * sc);
        float r[8];
        up2(a[0],r[0],r[1]); up2(a[1],r[2],r[3]); up2(a[2],r[4],r[5]); up2(a[3],r[6],r[7]);
        float* dst = sm + XBUF_OFF + lane * 60 + w * 8;
        #pragma unroll
        for (int q = 0; q < 8; ++q) dst[q] = fmaxf(fmaf(r[q], sc, bi), 0.f);
    }
    __syncthreads();

    // ============ Stage C1: v (warps 0-6), q & k (warp 7) ============
    if (w < 7) {
        float bias = v_b[lane];
        ull a[4]; a[0]=a[1]=a[2]=a[3]=pk2(bias,bias);
        const float* xb = sm + XBUF_OFF + w * 8;
        #pragma unroll 4
        for (int in2 = 0; in2 < 32; ++in2) {
            float wv = sm[VTW_OFF + in2 * 32 + (lane ^ (in2 & 31))];
            g8(a, xb + in2 * 60, wv);
        }
        float r[8];
        up2(a[0],r[0],r[1]); up2(a[1],r[2],r[3]); up2(a[2],r[4],r[5]); up2(a[3],r[6],r[7]);
        #pragma unroll
        for (int q = 0; q < 8; ++q) sm[VT_OFF + (w * 8 + q) * 32 + lane] = r[q];
    } else if (lane < 28) {
        int d = lane / 7, p = lane - d * 7;
        const float* xb = sm + XBUF_OFF + p * 8;
        #pragma unroll
        for (int pass = 0; pass < 2; ++pass) {
            const float* W = sm + (pass ? KW_OFF : QW_OFF) + d * 33;
            float bias = pass ? k_b[d] : q_b[d];
            ull a[4]; a[0]=a[1]=a[2]=a[3]=pk2(bias,bias);
            for (int in2 = 0; in2 < 32; ++in2) g8(a, xb + in2 * 60, W[in2]);
            float r[8];
            up2(a[0],r[0],r[1]); up2(a[1],r[2],r[3]); up2(a[2],r[4],r[5]); up2(a[3],r[6],r[7]);
            float* dst = sm + (pass ? KT_OFF : QT_OFF) + d * 60 + p * 8;
            #pragma unroll
            for (int q = 0; q < 8; ++q) dst[q] = r[q];
        }
    }
    __syncthreads();

    // ============ Stage C2: S[i][j] = sum_d q[d][i] k[d][j]. warp=i-octet, lane=j ==
    if (w < 7) {
        int i0 = w * 8;
        #pragma unroll
        for (int seg = 0; seg < 2; ++seg) {
            int j = seg * 32 + lane;
            if (j < 56) {
                ull a[4] = {0,0,0,0};
                #pragma unroll
                for (int d = 0; d < 4; ++d) {
                    float kv = sm[KT_OFF + d * 60 + j];
                    g8(a, sm + QT_OFF + d * 60 + i0, kv);
                }
                float r[8];
                up2(a[0],r[0],r[1]); up2(a[1],r[2],r[3]); up2(a[2],r[4],r[5]); up2(a[3],r[6],r[7]);
                #pragma unroll
                for (int q = 0; q < 8; ++q) sm[S_OFF + (i0 + q) * 60 + j] = r[q];
            }
        }
    }
    __syncthreads();

    // ============ softmax rows, write transposed attnT[j][i] ============
    if (t < 56) {
        float* row = sm + S_OFF + t * 60;
        const float4* r4 = (const float4*)row;
        float m = -1e30f;
        #pragma unroll
        for (int k = 0; k < 14; ++k) {
            float4 vv = r4[k];
            m = fmaxf(m, fmaxf(fmaxf(vv.x, vv.y), fmaxf(vv.z, vv.w)));
        }
        float ssum = 0.f;
        #pragma unroll 8
        for (int j = 0; j < 56; ++j) { float e = __expf(row[j] - m); row[j] = e; ssum += e; }
        float inv = 1.f / ssum;
        #pragma unroll 8
        for (int j = 0; j < 56; ++j) sm[ATT_OFF + j * 60 + t] = row[j] * inv;
    }
    __syncthreads();

    // ============ Stage C3: out[c][i] = sum_j v[j][c]*attnT[j][i]; x += gamma*out ==
    if (w < 7) {
        int i0 = w * 8;
        ull a[4] = {0,0,0,0};
        #pragma unroll 4
        for (int j = 0; j < 56; ++j) {
            float vv = sm[VT_OFF + j * 32 + lane];
            g8(a, sm + ATT_OFF + j * 60 + i0, vv);
        }
        float r[8];
        up2(a[0],r[0],r[1]); up2(a[1],r[2],r[3]); up2(a[2],r[4],r[5]); up2(a[3],r[6],r[7]);
        float g = gamma[0];
        float* xr = sm + XBUF_OFF + lane * 60 + i0;
        #pragma unroll
        for (int q = 0; q < 8; ++q) xr[q] = fmaf(g, r[q], xr[q]);
    }
    __syncthreads();

    // ============ Stage D: LayerNorm over 1792 ============
    float vals[7];
    {
        float s1 = 0.f, s2 = 0.f;
        #pragma unroll
        for (int k = 0; k < 7; ++k) {
            int v = t + k * 256;
            int c = v / 56, s = v - c * 56;
            float x = sm[XBUF_OFF + c * 60 + s];
            vals[k] = x; s1 += x; s2 = fmaf(x, x, s2);
        }
        #pragma unroll
        for (int off = 16; off; off >>= 1) {
            s1 += __shfl_xor_sync(0xffffffffu, s1, off);
            s2 += __shfl_xor_sync(0xffffffffu, s2, off);
        }
        if (lane == 0) { red[w] = s1; red[8 + w] = s2; }
        __syncthreads();
        if (t == 0) {
            float S1 = 0.f, S2 = 0.f;
            for (int k = 0; k < 8; ++k) { S1 += red[k]; S2 += red[8 + k]; }
            float mu = S1 * (1.f / 1792.f);
            float var = S2 * (1.f / 1792.f) - mu * mu;
            red[16] = mu; red[17] = rsqrtf(var + EPSV);
        }
        __syncthreads();
        float mu = red[16], inv = red[17];
        #pragma unroll
        for (int k = 0; k < 7; ++k) {
            int v = t + k * 256;
            vals[k] = (vals[k] - mu) * inv * ln_w[v] + ln_b[v];
        }
    }
    __syncthreads();   // all xbuf/attn reads done; regions reusable

    // zero pads of xpadA/xpadB; stage w_res half 1 (in-ch 0..15)
    for (int idx = t; idx < 6912; idx += 256) {
        float* base = (idx < 3456) ? (sm + XPA_OFF) : (sm + XPB_OFF - 3456);
        base[idx] = 0.f;
    }
    for (int idx = t; idx < 4608; idx += 256) {
        int o = idx / 144, r = idx - o * 144;
        sm[WREG_OFF + r * 32 + (o ^ (r & 31))] = w_res[o * 288 + r];
    }
    __syncthreads();
    #pragma unroll
    for (int k = 0; k < 7; ++k) {   // scatter LN output into padded xpadA
        int v = t + k * 256;
        int c = v / 56, s = v - c * 56, p = s >> 3, q = s & 7;
        sm[XPA_OFF + c * 108 + (p + 1) * 12 + (q + 1)] = vals[k];
    }
    __syncthreads();

    // ============ Stage E: residual 3x3 conv 32->32 (+BN+ReLU+res). warp=p, lane=o =
    ull e[4] = {0,0,0,0};
    if (w < 7) conv16(e, sm + XPA_OFF, sm + WREG_OFF, 32, 31, lane, w);
    __syncthreads();
    for (int idx = t; idx < 4608; idx += 256) {    // stage w_res half 2
        int o = idx / 144, r = idx - o * 144;
        sm[WREG_OFF + r * 32 + (o ^ (r & 31))] = w_res[o * 288 + 144 + r];
    }
    __syncthreads();
    if (w < 7) {
        conv16(e, sm + XPA_OFF + 16 * 108, sm + WREG_OFF, 32, 31, lane, w);
        float sc = bnres_w[lane] * rsqrtf(bnres_v[lane] + EPSV);
        float bi = fmaf(b_res[lane], sc, bnres_b[lane] - bnres_m[lane] * sc);
        float r[8];
        up2(e[0],r[0],r[1]); up2(e[1],r[2],r[3]); up2(e[2],r[4],r[5]); up2(e[3],r[6],r[7]);
        const float* rs = sm + XPA_OFF + lane * 108 + (w + 1) * 12 + 1;
        float* db = sm + XPB_OFF + lane * 108 + (w + 1) * 12 + 1;
        #pragma unroll
        for (int q = 0; q < 8; ++q)
            db[q] = fmaxf(fmaf(r[q], sc, bi), 0.f) + rs[q];
    }
    __syncthreads();

    // stage w1T (two half-blocks, 16-wide, offset 2320 apart) + w2
    for (int idx = t; idx < 4608; idx += 256) {
        int o = idx / 288, rr = idx - o * 288;
        int half = rr / 144, rp = rr - half * 144;
        sm[WREG_OFF + half * 2320 + rp * 16 + (o ^ (rp & 15))] = w1[idx];
    }
    if (t < 144) sm[W2_OFF + t] = w2[t];
    __syncthreads();

    // ============ Stage F: conv1 3x3 32->16 + BN + ReLU. lane halves split in-ch ===
    if (w < 7) {
        int o16 = lane & 15, half = lane >> 4;
        ull f[4] = {0,0,0,0};
        conv16(f, sm + XPB_OFF + half * 1728, sm + WREG_OFF + half * 2320, 16, 15, o16, w);
        #pragma unroll
        for (int m = 0; m < 4; ++m) {
            ull other = __shfl_xor_sync(0xffffffffu, f[m], 16);
            f[m] = add2(f[m], other);
        }
        if (half == 0) {
            float sc = bn1_w[o16] * rsqrtf(bn1_v[o16] + EPSV);
            float bi = fmaf(b1[o16], sc, bn1_b[o16] - bn1_m[o16] * sc);
            float r[8];
            up2(f[0],r[0],r[1]); up2(f[1],r[2],r[3]); up2(f[2],r[4],r[5]); up2(f[3],r[6],r[7]);
            float* dst = sm + XPA_OFF + o16 * 108 + (w + 1) * 12 + 1;
            #pragma unroll
            for (int q = 0; q < 8; ++q) dst[q] = fmaxf(fmaf(r[q], sc, bi), 0.f);
        }
    }
    __syncthreads();

    // ============ Stage G: conv2 3x3 16->1 ============
    if (t < 56) {
        int p = t >> 3, q = t & 7;
        float acc2 = b2[0];
        #pragma unroll 4
        for (int i = 0; i < 16; ++i) {
            const float* xc = sm + XPA_OFF + i * 108 + p * 12 + q;
            const float* wg = sm + W2_OFF + i * 9;
            acc2 = fmaf(wg[0], xc[0],  acc2);
            acc2 = fmaf(wg[1], xc[1],  acc2);
            acc2 = fmaf(wg[2], xc[2],  acc2);
            acc2 = fmaf(wg[3], xc[12], acc2);
            acc2 = fmaf(wg[4], xc[13], acc2);
            acc2 = fmaf(wg[5], xc[14], acc2);
            acc2 = fmaf(wg[6], xc[24], acc2);
            acc2 = fmaf(wg[7], xc[25], acc2);
            acc2 = fmaf(wg[8], xc[26], acc2);
        }
        out[(size_t)b * 56 + t] = acc2;
    }
}

extern "C" void kernel_launch(void* const* d_in, const int* in_sizes, int n_in,
                              void* d_out, int out_size) {
    const float* mg      = (const float*)d_in[0];
    const float* w_cr    = (const float*)d_in[1];
    const float* b_cr    = (const float*)d_in[2];
    const float* bnr_w   = (const float*)d_in[3];
    const float* bnr_b   = (const float*)d_in[4];
    const float* bnr_m   = (const float*)d_in[5];
    const float* bnr_v   = (const float*)d_in[6];
    const float* q_w     = (const float*)d_in[7];
    const float* q_b     = (const float*)d_in[8];
    const float* k_w     = (const float*)d_in[9];
    const float* k_b     = (const float*)d_in[10];
    const float* v_w     = (const float*)d_in[11];
    const float* v_b     = (const float*)d_in[12];
    const float* gamma   = (const float*)d_in[13];
    const float* ln_w    = (const float*)d_in[14];
    const float* ln_b    = (const float*)d_in[15];
    const float* w_res   = (const float*)d_in[16];
    const float* b_res   = (const float*)d_in[17];
    const float* bnres_w = (const float*)d_in[18];
    const float* bnres_b = (const float*)d_in[19];
    const float* bnres_m = (const float*)d_in[20];
    const float* bnres_v = (const float*)d_in[21];
    const float* w1      = (const float*)d_in[22];
    const float* b1      = (const float*)d_in[23];
    const float* bn1_w   = (const float*)d_in[24];
    const float* bn1_b   = (const float*)d_in[25];
    const float* bn1_m   = (const float*)d_in[26];
    const float* bn1_v   = (const float*)d_in[27];
    const float* w2      = (const float*)d_in[28];
    const float* b2      = (const float*)d_in[29];

    int B = in_sizes[0] / 32768;
    size_t smem_bytes = SMEM_FLOATS * sizeof(float);
    cudaFuncSetAttribute(occ_fused_kernel,
                         cudaFuncAttributeMaxDynamicSharedMemorySize, (int)smem_bytes);
    occ_fused_kernel<<<B, 256, smem_bytes>>>(
        mg, w_cr, b_cr, bnr_w, bnr_b, bnr_m, bnr_v,
        q_w, q_b, k_w, k_b, v_w, v_b, gamma, ln_w, ln_b,
        w_res, b_res, bnres_w, bnres_b, bnres_m, bnres_v,
        w1, b1, bn1_w, bn1_b, bn1_m, bn1_v, w2, b2,
        (float*)d_out);
}

// round 5
// speedup vs baseline: 1.3286x; 1.1271x over previous
#include <cuda_runtime.h>

#define EPSV 1e-5f
typedef unsigned long long ull;

// ---------------- shared memory layout (float offsets) ----------------
// Phase 1:
//   [0,7168)      pooled[128][56]  -> later QT(240)+KT(240)+VT(1792)+S(56x60)
//   [7168,11392)  wcrT[128][33]    -> later attnT[56][60] (3360)
//   [11392,12448) vTw[32][33]
//   [12448,12712) qw[4][33], kw[4][33]
//   [12712,14632) xbuf[32][60]
// Phase 2:
//   [0,3456)      xpadA[32][9][12]
//   [3456,5760)   shA[32][9][8]   (shifted copy of xpadA cols 1..8)
//   [5760,9216)   xpadB[32][9][12]
//   [9216,11520)  shB[32][9][8]
//   [11520,16416) weights: wresT half [144][33]=4752; later w1T 2x[144][17]=4896
//   [16416,16560) w2 (144)
// [16560,16592)   RED scratch
#define POOL_OFF 0
#define QT_OFF   0
#define KT_OFF   240
#define VT_OFF   480
#define S_OFF    2272
#define WCRT_OFF 7168
#define ATT_OFF  7168
#define VTW_OFF  11392
#define QW_OFF   12448
#define KW_OFF   12580
#define XBUF_OFF 12712

#define XPA_OFF  0
#define SHA_OFF  3456
#define XPB_OFF  5760
#define SHB_OFF  9216
#define WR2_OFF  11520
#define W2_OFF   16416
#define RED_OFF  16560
#define SMEM_FLOATS 16592

// ---------------- packed f32x2 helpers ----------------
__device__ __forceinline__ ull pk2(float x, float y) {
    ull r; asm("mov.b64 %0, {%1, %2};" : "=l"(r) : "f"(x), "f"(y)); return r;
}
__device__ __forceinline__ void up2(ull v, float& x, float& y) {
    asm("mov.b64 {%0, %1}, %2;" : "=f"(x), "=f"(y) : "l"(v));
}
__device__ __forceinline__ ull fma2(ull a, ull b, ull c) {
    ull r; asm("fma.rn.f32x2 %0, %1, %2, %3;" : "=l"(r) : "l"(a), "l"(b), "l"(c)); return r;
}
__device__ __forceinline__ ull add2(ull a, ull b) {
    ull r; asm("add.rn.f32x2 %0, %1, %2;" : "=l"(r) : "l"(a), "l"(b)); return r;
}

// 8-wide GEMM step: acc[4] += w * x[0..7], x warp-uniform
__device__ __forceinline__ void g8(ull acc[4], const float* __restrict__ x, float wv) {
    ulonglong2 A = *(const ulonglong2*)(x);
    ulonglong2 B = *(const ulonglong2*)(x + 4);
    ull wp = pk2(wv, wv);
    acc[0] = fma2(wp, A.x, acc[0]); acc[1] = fma2(wp, A.y, acc[1]);
    acc[2] = fma2(wp, B.x, acc[2]); acc[3] = fma2(wp, B.y, acc[3]);
}

// 3x3 conv over 16 input channels, output row p (8 cols), acc[4] f32x2 pairs.
// xb: padded rows (12 floats), sb: shifted rows (8 floats, = cols 1..8).
// wb: transposed weights, stride ws per tap, lane offset o. All LDS, no repacks.
__device__ __forceinline__ void conv16(ull acc[4], const float* __restrict__ xb,
                                       const float* __restrict__ sb,
                                       const float* __restrict__ wb, int ws,
                                       int o, int p) {
    #pragma unroll 2
    for (int ch = 0; ch < 16; ++ch) {
        #pragma unroll
        for (int r = 0; r < 3; ++r) {
            const float* row  = xb + ch * 108 + (p + r) * 12;
            const float* srow = sb + ch * 72 + (p + r) * 8;
            ulonglong2 E01 = *(const ulonglong2*)(row);       // x0..x3
            ulonglong2 E23 = *(const ulonglong2*)(row + 4);   // x4..x7
            ull        E4  = *(const ull*)(row + 8);          // x8,x9
            ulonglong2 O01 = *(const ulonglong2*)(srow);      // x1..x4
            ulonglong2 O23 = *(const ulonglong2*)(srow + 4);  // x5..x8
            const float* wp = wb + (ch * 9 + r * 3) * ws + o;
            float wv0 = wp[0], wv1 = wp[ws], wv2 = wp[2 * ws];
            ull w0 = pk2(wv0, wv0), w1 = pk2(wv1, wv1), w2 = pk2(wv2, wv2);
            acc[0] = fma2(w0, E01.x, acc[0]); acc[1] = fma2(w0, E01.y, acc[1]);
            acc[2] = fma2(w0, E23.x, acc[2]); acc[3] = fma2(w0, E23.y, acc[3]);
            acc[0] = fma2(w1, O01.x, acc[0]); acc[1] = fma2(w1, O01.y, acc[1]);
            acc[2] = fma2(w1, O23.x, acc[2]); acc[3] = fma2(w1, O23.y, acc[3]);
            acc[0] = fma2(w2, E01.y, acc[0]); acc[1] = fma2(w2, E23.x, acc[1]);
            acc[2] = fma2(w2, E23.y, acc[2]); acc[3] = fma2(w2, E4,    acc[3]);
        }
    }
}

__global__ void __launch_bounds__(256, 3) occ_fused_kernel(
    const float* __restrict__ mg,
    const float* __restrict__ w_cr, const float* __restrict__ b_cr,
    const float* __restrict__ bnr_w, const float* __restrict__ bnr_b,
    const float* __restrict__ bnr_m, const float* __restrict__ bnr_v,
    const float* __restrict__ q_w,  const float* __restrict__ q_b,
    const float* __restrict__ k_w,  const float* __restrict__ k_b,
    const float* __restrict__ v_w,  const float* __restrict__ v_b,
    const float* __restrict__ gamma,
    const float* __restrict__ ln_w, const float* __restrict__ ln_b,
    const float* __restrict__ w_res, const float* __restrict__ b_res,
    const float* __restrict__ bnres_w, const float* __restrict__ bnres_b,
    const float* __restrict__ bnres_m, const float* __restrict__ bnres_v,
    const float* __restrict__ w1,  const float* __restrict__ b1,
    const float* __restrict__ bn1_w, const float* __restrict__ bn1_b,
    const float* __restrict__ bn1_m, const float* __restrict__ bn1_v,
    const float* __restrict__ w2,  const float* __restrict__ b2,
    float* __restrict__ out)
{
    extern __shared__ float sm[];
    const int t = threadIdx.x;
    const int b = blockIdx.x;
    const int w = t >> 5;
    const int lane = t & 31;
    float* red = sm + RED_OFF;

    // ============ Stage A: adaptive pool 16x16 -> 7x8 + stage phase-1 weights ======
    {
        const float* in = mg + (size_t)b * 32768;
        int c = t / 56, s = t - c * 56;        // one division, then incremental
        for (int idx = t; idx < 7168; idx += 256) {
            int p = s >> 3, q = s & 7;
            int r0 = (p * 16) / 7;
            int r1 = ((p + 1) * 16 + 6) / 7;
            const float2* bp = (const float2*)(in + c * 256 + q * 2);
            float acc = 0.f;
            for (int r = r0; r < r1; ++r) { float2 v2 = bp[r * 8]; acc += v2.x + v2.y; }
            sm[POOL_OFF + idx] = acc * (0.5f / (float)(r1 - r0));
            s += 32; c += 4; if (s >= 56) { s -= 56; ++c; }
        }
        for (int idx = t; idx < 4096; idx += 256) {       // wcrT[c][o], stride 33
            int o = idx >> 7, cc = idx & 127;
            sm[WCRT_OFF + cc * 33 + o] = w_cr[idx];
        }
        for (int idx = t; idx < 1024; idx += 256) {       // vTw[in][o], stride 33
            int o = idx >> 5, in2 = idx & 31;
            sm[VTW_OFF + in2 * 33 + o] = v_w[idx];
        }
        if (t < 128) {
            int d = t >> 5, in2 = t & 31;
            sm[QW_OFF + d * 33 + in2] = q_w[t];
            sm[KW_OFF + d * 33 + in2] = k_w[t];
        }
    }
    __syncthreads();

    // ============ Stage B: 1x1 128->32 + BN + ReLU. warp=p, lane=o ============
    if (w < 7) {
        ull a[4] = {0,0,0,0};
        const float* xb = sm + POOL_OFF + w * 8;
        const float* wc = sm + WCRT_OFF + lane;
        #pragma unroll 4
        for (int c = 0; c < 128; ++c)
            g8(a, xb + c * 56, wc[c * 33]);
        float sc = bnr_w[lane] * rsqrtf(bnr_v[lane] + EPSV);
        float bi = fmaf(b_cr[lane], sc, bnr_b[lane] - bnr_m[lane] * sc);
        float r[8];
        up2(a[0],r[0],r[1]); up2(a[1],r[2],r[3]); up2(a[2],r[4],r[5]); up2(a[3],r[6],r[7]);
        float* dst = sm + XBUF_OFF + lane * 60 + w * 8;
        #pragma unroll
        for (int q = 0; q < 8; ++q) dst[q] = fmaxf(fmaf(r[q], sc, bi), 0.f);
    }
    __syncthreads();

    // ============ Stage C1: v (warps 0-6), q & k (warp 7) ============
    if (w < 7) {
        float bias = v_b[lane];
        ull a[4]; a[0]=a[1]=a[2]=a[3]=pk2(bias,bias);
        const float* xb = sm + XBUF_OFF + w * 8;
        const float* wv2p = sm + VTW_OFF + lane;
        #pragma unroll 4
        for (int in2 = 0; in2 < 32; ++in2)
            g8(a, xb + in2 * 60, wv2p[in2 * 33]);
        float r[8];
        up2(a[0],r[0],r[1]); up2(a[1],r[2],r[3]); up2(a[2],r[4],r[5]); up2(a[3],r[6],r[7]);
        #pragma unroll
        for (int q = 0; q < 8; ++q) sm[VT_OFF + (w * 8 + q) * 32 + lane] = r[q];
    } else if (lane < 28) {
        int d = lane / 7, p = lane - d * 7;
        const float* xb = sm + XBUF_OFF + p * 8;
        #pragma unroll
        for (int pass = 0; pass < 2; ++pass) {
            const float* W = sm + (pass ? KW_OFF : QW_OFF) + d * 33;
            float bias = pass ? k_b[d] : q_b[d];
            ull a[4]; a[0]=a[1]=a[2]=a[3]=pk2(bias,bias);
            for (int in2 = 0; in2 < 32; ++in2) g8(a, xb + in2 * 60, W[in2]);
            float r[8];
            up2(a[0],r[0],r[1]); up2(a[1],r[2],r[3]); up2(a[2],r[4],r[5]); up2(a[3],r[6],r[7]);
            float* dst = sm + (pass ? KT_OFF : QT_OFF) + d * 60 + p * 8;
            #pragma unroll
            for (int q = 0; q < 8; ++q) dst[q] = r[q];
        }
    }
    __syncthreads();

    // ============ Stage C2: S[i][j] = sum_d q[d][i] k[d][j] ============
    if (w < 7) {
        int i0 = w * 8;
        #pragma unroll
        for (int seg = 0; seg < 2; ++seg) {
            int j = seg * 32 + lane;
            if (j < 56) {
                ull a[4] = {0,0,0,0};
                #pragma unroll
                for (int d = 0; d < 4; ++d)
                    g8(a, sm + QT_OFF + d * 60 + i0, sm[KT_OFF + d * 60 + j]);
                float r[8];
                up2(a[0],r[0],r[1]); up2(a[1],r[2],r[3]); up2(a[2],r[4],r[5]); up2(a[3],r[6],r[7]);
                #pragma unroll
                for (int q = 0; q < 8; ++q) sm[S_OFF + (i0 + q) * 60 + j] = r[q];
            }
        }
    }
    __syncthreads();

    // ============ softmax rows, write transposed attnT[j][i] ============
    if (t < 56) {
        float* row = sm + S_OFF + t * 60;
        const float4* r4 = (const float4*)row;
        float m = -1e30f;
        #pragma unroll
        for (int k = 0; k < 14; ++k) {
            float4 vv = r4[k];
            m = fmaxf(m, fmaxf(fmaxf(vv.x, vv.y), fmaxf(vv.z, vv.w)));
        }
        float ssum = 0.f;
        #pragma unroll 8
        for (int j = 0; j < 56; ++j) { float e = __expf(row[j] - m); row[j] = e; ssum += e; }
        float inv = 1.f / ssum;
        #pragma unroll 8
        for (int j = 0; j < 56; ++j) sm[ATT_OFF + j * 60 + t] = row[j] * inv;
    }
    __syncthreads();

    // ============ Stage C3: out[c][i] = sum_j v[j][c]*attnT[j][i]; x += gamma*out ==
    if (w < 7) {
        int i0 = w * 8;
        ull a[4] = {0,0,0,0};
        #pragma unroll 4
        for (int j = 0; j < 56; ++j)
            g8(a, sm + ATT_OFF + j * 60 + i0, sm[VT_OFF + j * 32 + lane]);
        float r[8];
        up2(a[0],r[0],r[1]); up2(a[1],r[2],r[3]); up2(a[2],r[4],r[5]); up2(a[3],r[6],r[7]);
        float g = gamma[0];
        float* xr = sm + XBUF_OFF + lane * 60 + i0;
        #pragma unroll
        for (int q = 0; q < 8; ++q) xr[q] = fmaf(g, r[q], xr[q]);
    }
    __syncthreads();

    // ============ Stage D: LayerNorm over 1792 ============
    float vals[7];
    int lc[7], lp[7], lq[7];
    {
        float s1 = 0.f, s2 = 0.f;
        int c = t / 56, s = t - c * 56;
        #pragma unroll
        for (int k = 0; k < 7; ++k) {
            lc[k] = c; lp[k] = s >> 3; lq[k] = s & 7;
            float x = sm[XBUF_OFF + c * 60 + s];
            vals[k] = x; s1 += x; s2 = fmaf(x, x, s2);
            s += 32; c += 4; if (s >= 56) { s -= 56; ++c; }
        }
        #pragma unroll
        for (int off = 16; off; off >>= 1) {
            s1 += __shfl_xor_sync(0xffffffffu, s1, off);
            s2 += __shfl_xor_sync(0xffffffffu, s2, off);
        }
        if (lane == 0) { red[w] = s1; red[8 + w] = s2; }
        __syncthreads();
        if (t == 0) {
            float S1 = 0.f, S2 = 0.f;
            for (int k = 0; k < 8; ++k) { S1 += red[k]; S2 += red[8 + k]; }
            float mu = S1 * (1.f / 1792.f);
            float var = S2 * (1.f / 1792.f) - mu * mu;
            red[16] = mu; red[17] = rsqrtf(var + EPSV);
        }
        __syncthreads();
        float mu = red[16], inv = red[17];
        #pragma unroll
        for (int k = 0; k < 7; ++k) {
            int v = t + k * 256;
            vals[k] = (vals[k] - mu) * inv * ln_w[v] + ln_b[v];
        }
    }
    __syncthreads();   // all phase-1 activation reads done

    // zero xpadA/shA/xpadB/shB ([0,11520) contiguous) + stage w_res half 1
    {
        float4 z4 = make_float4(0.f, 0.f, 0.f, 0.f);
        float4* z = (float4*)sm;
        for (int idx = t; idx < 2880; idx += 256) z[idx] = z4;
        for (int idx = t; idx < 4608; idx += 256) {
            int o = idx / 144, r = idx - o * 144;
            sm[WR2_OFF + r * 33 + o] = w_res[o * 288 + r];
        }
    }
    __syncthreads();
    #pragma unroll
    for (int k = 0; k < 7; ++k) {   // scatter LN output into xpadA + shifted shA
        int c = lc[k], p = lp[k], q = lq[k];
        sm[XPA_OFF + c * 108 + (p + 1) * 12 + (q + 1)] = vals[k];
        sm[SHA_OFF + c * 72 + (p + 1) * 8 + q] = vals[k];
    }
    __syncthreads();

    // ============ Stage E: residual 3x3 conv 32->32 (+BN+ReLU+res) ============
    ull e[4] = {0,0,0,0};
    if (w < 7) conv16(e, sm + XPA_OFF, sm + SHA_OFF, sm + WR2_OFF, 33, lane, w);
    __syncthreads();
    for (int idx = t; idx < 4608; idx += 256) {    // stage w_res half 2
        int o = idx / 144, r = idx - o * 144;
        sm[WR2_OFF + r * 33 + o] = w_res[o * 288 + 144 + r];
    }
    __syncthreads();
    if (w < 7) {
        conv16(e, sm + XPA_OFF + 16 * 108, sm + SHA_OFF + 16 * 72, sm + WR2_OFF, 33, lane, w);
        float sc = bnres_w[lane] * rsqrtf(bnres_v[lane] + EPSV);
        float bi = fmaf(b_res[lane], sc, bnres_b[lane] - bnres_m[lane] * sc);
        float r[8];
        up2(e[0],r[0],r[1]); up2(e[1],r[2],r[3]); up2(e[2],r[4],r[5]); up2(e[3],r[6],r[7]);
        const float* rs = sm + XPA_OFF + lane * 108 + (w + 1) * 12 + 1;
        float* db = sm + XPB_OFF + lane * 108 + (w + 1) * 12 + 1;
        float* sb = sm + SHB_OFF + lane * 72 + (w + 1) * 8;
        #pragma unroll
        for (int q = 0; q < 8; ++q) {
            float vv = fmaxf(fmaf(r[q], sc, bi), 0.f) + rs[q];
            db[q] = vv; sb[q] = vv;
        }
    }
    __syncthreads();

    // stage w1T (two halves, stride 17) + w2
    for (int idx = t; idx < 4608; idx += 256) {
        int o = idx / 288, rr = idx - o * 288;
        int half = (rr >= 144) ? 1 : 0, rp = rr - half * 144;
        sm[WR2_OFF + half * 2448 + rp * 17 + o] = w1[idx];
    }
    if (t < 144) sm[W2_OFF + t] = w2[t];
    __syncthreads();

    // ============ Stage F: conv1 3x3 32->16 + BN + ReLU (lane halves split in-ch) ==
    if (w < 7) {
        int o16 = lane & 15, half = lane >> 4;
        ull f[4] = {0,0,0,0};
        conv16(f, sm + XPB_OFF + half * 1728, sm + SHB_OFF + half * 1152,
               sm + WR2_OFF + half * 2448, 17, o16, w);
        #pragma unroll
        for (int m = 0; m < 4; ++m) {
            ull other = __shfl_xor_sync(0xffffffffu, f[m], 16);
            f[m] = add2(f[m], other);
        }
        if (half == 0) {
            float sc = bn1_w[o16] * rsqrtf(bn1_v[o16] + EPSV);
            float bi = fmaf(b1[o16], sc, bn1_b[o16] - bn1_m[o16] * sc);
            float r[8];
            up2(f[0],r[0],r[1]); up2(f[1],r[2],r[3]); up2(f[2],r[4],r[5]); up2(f[3],r[6],r[7]);
            float* dst = sm + XPA_OFF + o16 * 108 + (w + 1) * 12 + 1;
            #pragma unroll
            for (int q = 0; q < 8; ++q) dst[q] = fmaxf(fmaf(r[q], sc, bi), 0.f);
        }
    }
    __syncthreads();

    // ============ Stage G: conv2 3x3 16->1 ============
    if (t < 56) {
        int p = t >> 3, q = t & 7;
        float acc2 = b2[0];
        #pragma unroll 4
        for (int i = 0; i < 16; ++i) {
            const float* xc = sm + XPA_OFF + i * 108 + p * 12 + q;
            const float* wg = sm + W2_OFF + i * 9;
            acc2 = fmaf(wg[0], xc[0],  acc2);
            acc2 = fmaf(wg[1], xc[1],  acc2);
            acc2 = fmaf(wg[2], xc[2],  acc2);
            acc2 = fmaf(wg[3], xc[12], acc2);
            acc2 = fmaf(wg[4], xc[13], acc2);
            acc2 = fmaf(wg[5], xc[14], acc2);
            acc2 = fmaf(wg[6], xc[24], acc2);
            acc2 = fmaf(wg[7], xc[25], acc2);
            acc2 = fmaf(wg[8], xc[26], acc2);
        }
        out[(size_t)b * 56 + t] = acc2;
    }
}

extern "C" void kernel_launch(void* const* d_in, const int* in_sizes, int n_in,
                              void* d_out, int out_size) {
    const float* mg      = (const float*)d_in[0];
    const float* w_cr    = (const float*)d_in[1];
    const float* b_cr    = (const float*)d_in[2];
    const float* bnr_w   = (const float*)d_in[3];
    const float* bnr_b   = (const float*)d_in[4];
    const float* bnr_m   = (const float*)d_in[5];
    const float* bnr_v   = (const float*)d_in[6];
    const float* q_w     = (const float*)d_in[7];
    const float* q_b     = (const float*)d_in[8];
    const float* k_w     = (const float*)d_in[9];
    const float* k_b     = (const float*)d_in[10];
    const float* v_w     = (const float*)d_in[11];
    const float* v_b     = (const float*)d_in[12];
    const float* gamma   = (const float*)d_in[13];
    const float* ln_w    = (const float*)d_in[14];
    const float* ln_b    = (const float*)d_in[15];
    const float* w_res   = (const float*)d_in[16];
    const float* b_res   = (const float*)d_in[17];
    const float* bnres_w = (const float*)d_in[18];
    const float* bnres_b = (const float*)d_in[19];
    const float* bnres_m = (const float*)d_in[20];
    const float* bnres_v = (const float*)d_in[21];
    const float* w1      = (const float*)d_in[22];
    const float* b1      = (const float*)d_in[23];
    const float* bn1_w   = (const float*)d_in[24];
    const float* bn1_b   = (const float*)d_in[25];
    const float* bn1_m   = (const float*)d_in[26];
    const float* bn1_v   = (const float*)d_in[27];
    const float* w2      = (const float*)d_in[28];
    const float* b2      = (const float*)d_in[29];

    int B = in_sizes[0] / 32768;
    size_t smem_bytes = SMEM_FLOATS * sizeof(float);
    cudaFuncSetAttribute(occ_fused_kernel,
                         cudaFuncAttributeMaxDynamicSharedMemorySize, (int)smem_bytes);
    occ_fused_kernel<<<B, 256, smem_bytes>>>(
        mg, w_cr, b_cr, bnr_w, bnr_b, bnr_m, bnr_v,
        q_w, q_b, k_w, k_b, v_w, v_b, gamma, ln_w, ln_b,
        w_res, b_res, bnres_w, bnres_b, bnres_m, bnres_v,
        w1, b1, bn1_w, bn1_b, bn1_m, bn1_v, w2, b2,
        (float*)d_out);
}

// round 6
// speedup vs baseline: 1.5775x; 1.1873x over previous
#include <cuda_runtime.h>

#define EPSV 1e-5f
typedef unsigned long long ull;

// ---------------- shared memory layout (float offsets), 14336 floats = 56KB --
// Phase 1:
//   [0,7168)      pooled[128][56]
//     after stage B (pooled dead): QT[4][60]@0, KT[4][60]@240, VT[56][32]@480,
//                                  S[56][60]@2272..5632, attnT[56][60]@5632..8992
//                                  RED@8992..9024
//   [7168,11392)  wcrT[128][33]   (dead after stage B)
//   [11392,12416) vTw[32][32]
//   [12416,14336) xbuf[32][60]
// Phase 2:
//   [0,3456)      xpadA[32][9][12]
//   [3456,5760)   shA[32][9][8]  (later aliased by shB after a sync)
//   [5760,9216)   xpadB[32][9][12]
//   [9216,13968)  wres half [144][33]=4752 ; later w1T 2x[144][17]=4896
//   [14112,14256) w2
#define POOL_OFF 0
#define QT_OFF   0
#define KT_OFF   240
#define VT_OFF   480
#define S_OFF    2272
#define ATT_OFF  5632
#define RED_OFF  8992
#define WCRT_OFF 7168
#define VTW_OFF  11392
#define XBUF_OFF 12416

#define XPA_OFF  0
#define SHA_OFF  3456
#define XPB_OFF  5760
#define SHB_OFF  3456
#define WR2_OFF  9216
#define W2_OFF   14112
#define SMEM_FLOATS 14336

// ---------------- packed f32x2 helpers ----------------
__device__ __forceinline__ ull pk2(float x, float y) {
    ull r; asm("mov.b64 %0, {%1, %2};" : "=l"(r) : "f"(x), "f"(y)); return r;
}
__device__ __forceinline__ void up2(ull v, float& x, float& y) {
    asm("mov.b64 {%0, %1}, %2;" : "=f"(x), "=f"(y) : "l"(v));
}
__device__ __forceinline__ ull fma2(ull a, ull b, ull c) {
    ull r; asm("fma.rn.f32x2 %0, %1, %2, %3;" : "=l"(r) : "l"(a), "l"(b), "l"(c)); return r;
}
__device__ __forceinline__ ull add2(ull a, ull b) {
    ull r; asm("add.rn.f32x2 %0, %1, %2;" : "=l"(r) : "l"(a), "l"(b)); return r;
}

// 8-wide GEMM step: acc[4] += w * x[0..7], x warp-uniform (broadcast LDS.128)
__device__ __forceinline__ void g8(ull acc[4], const float* __restrict__ x, float wv) {
    ulonglong2 A = *(const ulonglong2*)(x);
    ulonglong2 B = *(const ulonglong2*)(x + 4);
    ull wp = pk2(wv, wv);
    acc[0] = fma2(wp, A.x, acc[0]); acc[1] = fma2(wp, A.y, acc[1]);
    acc[2] = fma2(wp, B.x, acc[2]); acc[3] = fma2(wp, B.y, acc[3]);
}

// 3x3 conv over 16 input channels, output row p (8 cols), acc[4] f32x2 pairs.
__device__ __forceinline__ void conv16(ull acc[4], const float* __restrict__ xb,
                                       const float* __restrict__ sb,
                                       const float* __restrict__ wb, int ws,
                                       int o, int p) {
    #pragma unroll 2
    for (int ch = 0; ch < 16; ++ch) {
        #pragma unroll
        for (int r = 0; r < 3; ++r) {
            const float* row  = xb + ch * 108 + (p + r) * 12;
            const float* srow = sb + ch * 72 + (p + r) * 8;
            ulonglong2 E01 = *(const ulonglong2*)(row);       // x0..x3
            ulonglong2 E23 = *(const ulonglong2*)(row + 4);   // x4..x7
            ull        E4  = *(const ull*)(row + 8);          // x8,x9
            ulonglong2 O01 = *(const ulonglong2*)(srow);      // x1..x4
            ulonglong2 O23 = *(const ulonglong2*)(srow + 4);  // x5..x8
            const float* wp = wb + (ch * 9 + r * 3) * ws + o;
            float wv0 = wp[0], wv1 = wp[ws], wv2 = wp[2 * ws];
            ull w0 = pk2(wv0, wv0), w1 = pk2(wv1, wv1), w2 = pk2(wv2, wv2);
            acc[0] = fma2(w0, E01.x, acc[0]); acc[1] = fma2(w0, E01.y, acc[1]);
            acc[2] = fma2(w0, E23.x, acc[2]); acc[3] = fma2(w0, E23.y, acc[3]);
            acc[0] = fma2(w1, O01.x, acc[0]); acc[1] = fma2(w1, O01.y, acc[1]);
            acc[2] = fma2(w1, O23.x, acc[2]); acc[3] = fma2(w1, O23.y, acc[3]);
            acc[0] = fma2(w2, E01.y, acc[0]); acc[1] = fma2(w2, E23.x, acc[1]);
            acc[2] = fma2(w2, E23.y, acc[2]); acc[3] = fma2(w2, E4,    acc[3]);
        }
    }
}

__global__ void __launch_bounds__(256, 4) occ_fused_kernel(
    const float* __restrict__ mg,
    const float* __restrict__ w_cr, const float* __restrict__ b_cr,
    const float* __restrict__ bnr_w, const float* __restrict__ bnr_b,
    const float* __restrict__ bnr_m, const float* __restrict__ bnr_v,
    const float* __restrict__ q_w,  const float* __restrict__ q_b,
    const float* __restrict__ k_w,  const float* __restrict__ k_b,
    const float* __restrict__ v_w,  const float* __restrict__ v_b,
    const float* __restrict__ gamma,
    const float* __restrict__ ln_w, const float* __restrict__ ln_b,
    const float* __restrict__ w_res, const float* __restrict__ b_res,
    const float* __restrict__ bnres_w, const float* __restrict__ bnres_b,
    const float* __restrict__ bnres_m, const float* __restrict__ bnres_v,
    const float* __restrict__ w1,  const float* __restrict__ b1,
    const float* __restrict__ bn1_w, const float* __restrict__ bn1_b,
    const float* __restrict__ bn1_m, const float* __restrict__ bn1_v,
    const float* __restrict__ w2,  const float* __restrict__ b2,
    float* __restrict__ out)
{
    extern __shared__ float sm[];
    const int t = threadIdx.x;
    const int b = blockIdx.x;
    const int w = t >> 5;
    const int lane = t & 31;
    float* red = sm + RED_OFF;

    // ============ Stage A: adaptive pool 16x16 -> 7x8 + stage phase-1 weights ======
    {
        const float* in = mg + (size_t)b * 32768;
        int c = t / 56, s = t - c * 56;        // one division, then incremental
        for (int idx = t; idx < 7168; idx += 256) {
            int p = s >> 3, q = s & 7;
            int r0 = (p * 147) >> 6;                 // == (p*16)/7
            int r1 = ((p + 1) * 16 + 6) / 7;
            const float2* bp = (const float2*)(in + c * 256 + q * 2);
            float acc = 0.f;
            for (int r = r0; r < r1; ++r) { float2 v2 = bp[r * 8]; acc += v2.x + v2.y; }
            sm[POOL_OFF + idx] = acc * (0.5f / (float)(r1 - r0));
            s += 32; c += 4; if (s >= 56) { s -= 56; ++c; }
        }
        for (int idx = t; idx < 4096; idx += 256) {       // wcrT[c][o], stride 33
            int o = idx >> 7, cc = idx & 127;
            sm[WCRT_OFF + cc * 33 + o] = w_cr[idx];
        }
        for (int idx = t; idx < 1024; idx += 256) {       // vTw[in][o], stride 32
            int in2 = idx >> 5, o = idx & 31;             // conflict-free STS
            sm[VTW_OFF + in2 * 32 + o] = v_w[o * 32 + in2];
        }
    }
    __syncthreads();

    // ============ Stage B: 1x1 128->32 + BN + ReLU. warp=p, lane=o ============
    if (w < 7) {
        ull a[4] = {0,0,0,0};
        const float* xb = sm + POOL_OFF + w * 8;
        const float* wc = sm + WCRT_OFF + lane;
        #pragma unroll 4
        for (int c = 0; c < 128; ++c)
            g8(a, xb + c * 56, wc[c * 33]);
        float sc = bnr_w[lane] * rsqrtf(bnr_v[lane] + EPSV);
        float bi = fmaf(b_cr[lane], sc, bnr_b[lane] - bnr_m[lane] * sc);
        float r[8];
        up2(a[0],r[0],r[1]); up2(a[1],r[2],r[3]); up2(a[2],r[4],r[5]); up2(a[3],r[6],r[7]);
        float* dst = sm + XBUF_OFF + lane * 60 + w * 8;
        #pragma unroll
        for (int q = 0; q < 8; ++q) dst[q] = fmaxf(fmaf(r[q], sc, bi), 0.f);
    }
    __syncthreads();

    // ============ Stage C1: v (warps 0-6), q & k (warp 7, weights via gmem) =======
    if (w < 7) {
        float bias = v_b[lane];
        ull a[4]; a[0]=a[1]=a[2]=a[3]=pk2(bias,bias);
        const float* xb = sm + XBUF_OFF + w * 8;
        const float* wv2p = sm + VTW_OFF + lane;
        #pragma unroll 4
        for (int in2 = 0; in2 < 32; ++in2)
            g8(a, xb + in2 * 60, wv2p[in2 * 32]);
        float r[8];
        up2(a[0],r[0],r[1]); up2(a[1],r[2],r[3]); up2(a[2],r[4],r[5]); up2(a[3],r[6],r[7]);
        #pragma unroll
        for (int q = 0; q < 8; ++q) sm[VT_OFF + (w * 8 + q) * 32 + lane] = r[q];
    } else if (lane < 28) {
        int d = lane / 7, p = lane - d * 7;
        const float* xb = sm + XBUF_OFF + p * 8;
        #pragma unroll
        for (int pass = 0; pass < 2; ++pass) {
            const float* W = (pass ? k_w : q_w) + d * 32;
            float bias = pass ? k_b[d] : q_b[d];
            ull a[4]; a[0]=a[1]=a[2]=a[3]=pk2(bias,bias);
            for (int in2 = 0; in2 < 32; ++in2) g8(a, xb + in2 * 60, __ldg(W + in2));
            float r[8];
            up2(a[0],r[0],r[1]); up2(a[1],r[2],r[3]); up2(a[2],r[4],r[5]); up2(a[3],r[6],r[7]);
            float* dst = sm + (pass ? KT_OFF : QT_OFF) + d * 60 + p * 8;
            #pragma unroll
            for (int q = 0; q < 8; ++q) dst[q] = r[q];
        }
    }
    __syncthreads();

    // ============ Stage C2: S[i][j] = sum_d q[d][i] k[d][j] ============
    if (w < 7) {
        int i0 = w * 8;
        #pragma unroll
        for (int seg = 0; seg < 2; ++seg) {
            int j = seg * 32 + lane;
            if (j < 56) {
                ull a[4] = {0,0,0,0};
                #pragma unroll
                for (int d = 0; d < 4; ++d)
                    g8(a, sm + QT_OFF + d * 60 + i0, sm[KT_OFF + d * 60 + j]);
                float r[8];
                up2(a[0],r[0],r[1]); up2(a[1],r[2],r[3]); up2(a[2],r[4],r[5]); up2(a[3],r[6],r[7]);
                #pragma unroll
                for (int q = 0; q < 8; ++q) sm[S_OFF + (i0 + q) * 60 + j] = r[q];
            }
        }
    }
    __syncthreads();

    // ============ softmax rows, write transposed attnT[j][i] ============
    if (t < 56) {
        float* row = sm + S_OFF + t * 60;
        const float4* r4 = (const float4*)row;
        float m = -1e30f;
        #pragma unroll
        for (int k = 0; k < 14; ++k) {
            float4 vv = r4[k];
            m = fmaxf(m, fmaxf(fmaxf(vv.x, vv.y), fmaxf(vv.z, vv.w)));
        }
        float ssum = 0.f;
        #pragma unroll 8
        for (int j = 0; j < 56; ++j) { float e = __expf(row[j] - m); row[j] = e; ssum += e; }
        float inv = 1.f / ssum;
        #pragma unroll 8
        for (int j = 0; j < 56; ++j) sm[ATT_OFF + j * 60 + t] = row[j] * inv;
    }
    __syncthreads();

    // ============ Stage C3: out[c][i] = sum_j v[j][c]*attnT[j][i]; x += gamma*out ==
    if (w < 7) {
        int i0 = w * 8;
        ull a[4] = {0,0,0,0};
        #pragma unroll 4
        for (int j = 0; j < 56; ++j)
            g8(a, sm + ATT_OFF + j * 60 + i0, sm[VT_OFF + j * 32 + lane]);
        float r[8];
        up2(a[0],r[0],r[1]); up2(a[1],r[2],r[3]); up2(a[2],r[4],r[5]); up2(a[3],r[6],r[7]);
        float g = gamma[0];
        float* xr = sm + XBUF_OFF + lane * 60 + i0;
        #pragma unroll
        for (int q = 0; q < 8; ++q) xr[q] = fmaf(g, r[q], xr[q]);
    }
    __syncthreads();

    // ============ Stage D: LayerNorm over 1792 (vals bridge xbuf -> xpadA) ========
    float vals[7];
    {
        float s1 = 0.f, s2 = 0.f;
        int c = t / 56, s = t - c * 56;
        #pragma unroll
        for (int k = 0; k < 7; ++k) {
            float x = sm[XBUF_OFF + c * 60 + s];
            vals[k] = x; s1 += x; s2 = fmaf(x, x, s2);
            s += 32; c += 4; if (s >= 56) { s -= 56; ++c; }
        }
        #pragma unroll
        for (int off = 16; off; off >>= 1) {
            s1 += __shfl_xor_sync(0xffffffffu, s1, off);
            s2 += __shfl_xor_sync(0xffffffffu, s2, off);
        }
        if (lane == 0) { red[w] = s1; red[8 + w] = s2; }
        __syncthreads();
        if (t == 0) {
            float S1 = 0.f, S2 = 0.f;
            for (int k = 0; k < 8; ++k) { S1 += red[k]; S2 += red[8 + k]; }
            float mu = S1 * (1.f / 1792.f);
            float var = S2 * (1.f / 1792.f) - mu * mu;
            red[16] = mu; red[17] = rsqrtf(var + EPSV);
        }
        __syncthreads();
        float mu = red[16], inv = red[17];
        #pragma unroll
        for (int k = 0; k < 7; ++k) {
            int v = t + k * 256;
            vals[k] = (vals[k] - mu) * inv * ln_w[v] + ln_b[v];
        }
    }
    __syncthreads();   // all phase-1 activation reads done; xbuf dies below

    // zero xpadA/shA/xpadB ([0,9216)) + stage w_res half 1 (overwrites vTw/xbuf)
    {
        float4 z4 = make_float4(0.f, 0.f, 0.f, 0.f);
        float4* z = (float4*)sm;
        for (int idx = t; idx < 2304; idx += 256) z[idx] = z4;
        for (int idx = t; idx < 4608; idx += 256) {
            int o = idx / 144, r = idx - o * 144;
            sm[WR2_OFF + r * 33 + o] = w_res[o * 288 + r];
        }
    }
    __syncthreads();
    {
        int c = t / 56, s = t - c * 56;
        #pragma unroll
        for (int k = 0; k < 7; ++k) {   // scatter LN output into xpadA + shifted shA
            int p = s >> 3, q = s & 7;
            sm[XPA_OFF + c * 108 + (p + 1) * 12 + (q + 1)] = vals[k];
            sm[SHA_OFF + c * 72 + (p + 1) * 8 + q] = vals[k];
            s += 32; c += 4; if (s >= 56) { s -= 56; ++c; }
        }
    }
    __syncthreads();

    // ============ Stage E: residual 3x3 conv 32->32 (+BN+ReLU+res) ============
    ull e[4] = {0,0,0,0};
    if (w < 7) conv16(e, sm + XPA_OFF, sm + SHA_OFF, sm + WR2_OFF, 33, lane, w);
    __syncthreads();
    for (int idx = t; idx < 4608; idx += 256) {    // stage w_res half 2
        int o = idx / 144, r = idx - o * 144;
        sm[WR2_OFF + r * 33 + o] = w_res[o * 288 + 144 + r];
    }
    __syncthreads();
    float er[8];
    if (w < 7) {
        conv16(e, sm + XPA_OFF + 16 * 108, sm + SHA_OFF + 16 * 72, sm + WR2_OFF, 33, lane, w);
        float sc = bnres_w[lane] * rsqrtf(bnres_v[lane] + EPSV);
        float bi = fmaf(b_res[lane], sc, bnres_b[lane] - bnres_m[lane] * sc);
        float r[8];
        up2(e[0],r[0],r[1]); up2(e[1],r[2],r[3]); up2(e[2],r[4],r[5]); up2(e[3],r[6],r[7]);
        const float* rs = sm + XPA_OFF + lane * 108 + (w + 1) * 12 + 1;
        #pragma unroll
        for (int q = 0; q < 8; ++q)
            er[q] = fmaxf(fmaf(r[q], sc, bi), 0.f) + rs[q];
    }
    __syncthreads();   // all shA reads done; shB may overwrite shA region

    // write stage-E results (xpadB + shB) and stage w1T/w2 concurrently
    if (w < 7) {
        float* db = sm + XPB_OFF + lane * 108 + (w + 1) * 12 + 1;
        float* sb = sm + SHB_OFF + lane * 72 + (w + 1) * 8;
        #pragma unroll
        for (int q = 0; q < 8; ++q) { db[q] = er[q]; sb[q] = er[q]; }
    }
    for (int idx = t; idx < 4608; idx += 256) {    // w1T two halves, stride 17
        int o = idx / 288, rr = idx - o * 288;
        int half = (rr >= 144) ? 1 : 0, rp = rr - half * 144;
        sm[WR2_OFF + half * 2448 + rp * 17 + o] = w1[idx];
    }
    if (t < 144) sm[W2_OFF + t] = w2[t];
    __syncthreads();

    // ============ Stage F: conv1 3x3 32->16 + BN + ReLU (lane halves split in-ch) ==
    if (w < 7) {
        int o16 = lane & 15, half = lane >> 4;
        ull f[4] = {0,0,0,0};
        conv16(f, sm + XPB_OFF + half * 1728, sm + SHB_OFF + half * 1152,
               sm + WR2_OFF + half * 2448, 17, o16, w);
        #pragma unroll
        for (int m = 0; m < 4; ++m) {
            ull other = __shfl_xor_sync(0xffffffffu, f[m], 16);
            f[m] = add2(f[m], other);
        }
        if (half == 0) {
            float sc = bn1_w[o16] * rsqrtf(bn1_v[o16] + EPSV);
            float bi = fmaf(b1[o16], sc, bn1_b[o16] - bn1_m[o16] * sc);
            float r[8];
            up2(f[0],r[0],r[1]); up2(f[1],r[2],r[3]); up2(f[2],r[4],r[5]); up2(f[3],r[6],r[7]);
            float* dst = sm + XPA_OFF + o16 * 108 + (w + 1) * 12 + 1;
            #pragma unroll
            for (int q = 0; q < 8; ++q) dst[q] = fmaxf(fmaf(r[q], sc, bi), 0.f);
        }
    }
    __syncthreads();

    // ============ Stage G: conv2 3x3 16->1 ============
    if (t < 56) {
        int p = t >> 3, q = t & 7;
        float acc2 = b2[0];
        #pragma unroll 4
        for (int i = 0; i < 16; ++i) {
            const float* xc = sm + XPA_OFF + i * 108 + p * 12 + q;
            const float* wg = sm + W2_OFF + i * 9;
            acc2 = fmaf(wg[0], xc[0],  acc2);
            acc2 = fmaf(wg[1], xc[1],  acc2);
            acc2 = fmaf(wg[2], xc[2],  acc2);
            acc2 = fmaf(wg[3], xc[12], acc2);
            acc2 = fmaf(wg[4], xc[13], acc2);
            acc2 = fmaf(wg[5], xc[14], acc2);
            acc2 = fmaf(wg[6], xc[24], acc2);
            acc2 = fmaf(wg[7], xc[25], acc2);
            acc2 = fmaf(wg[8], xc[26], acc2);
        }
        out[(size_t)b * 56 + t] = acc2;
    }
}

extern "C" void kernel_launch(void* const* d_in, const int* in_sizes, int n_in,
                              void* d_out, int out_size) {
    const float* mg      = (const float*)d_in[0];
    const float* w_cr    = (const float*)d_in[1];
    const float* b_cr    = (const float*)d_in[2];
    const float* bnr_w   = (const float*)d_in[3];
    const float* bnr_b   = (const float*)d_in[4];
    const float* bnr_m   = (const float*)d_in[5];
    const float* bnr_v   = (const float*)d_in[6];
    const float* q_w     = (const float*)d_in[7];
    const float* q_b     = (const float*)d_in[8];
    const float* k_w     = (const float*)d_in[9];
    const float* k_b     = (const float*)d_in[10];
    const float* v_w     = (const float*)d_in[11];
    const float* v_b     = (const float*)d_in[12];
    const float* gamma   = (const float*)d_in[13];
    const float* ln_w    = (const float*)d_in[14];
    const float* ln_b    = (const float*)d_in[15];
    const float* w_res   = (const float*)d_in[16];
    const float* b_res   = (const float*)d_in[17];
    const float* bnres_w = (const float*)d_in[18];
    const float* bnres_b = (const float*)d_in[19];
    const float* bnres_m = (const float*)d_in[20];
    const float* bnres_v = (const float*)d_in[21];
    const float* w1      = (const float*)d_in[22];
    const float* b1      = (const float*)d_in[23];
    const float* bn1_w   = (const float*)d_in[24];
    const float* bn1_b   = (const float*)d_in[25];
    const float* bn1_m   = (const float*)d_in[26];
    const float* bn1_v   = (const float*)d_in[27];
    const float* w2      = (const float*)d_in[28];
    const float* b2      = (const float*)d_in[29];

    int B = in_sizes[0] / 32768;
    size_t smem_bytes = SMEM_FLOATS * sizeof(float);   // 57344 = 56KB -> 4 CTAs/SM
    cudaFuncSetAttribute(occ_fused_kernel,
                         cudaFuncAttributeMaxDynamicSharedMemorySize, (int)smem_bytes);
    occ_fused_kernel<<<B, 256, smem_bytes>>>(
        mg, w_cr, b_cr, bnr_w, bnr_b, bnr_m, bnr_v,
        q_w, q_b, k_w, k_b, v_w, v_b, gamma, ln_w, ln_b,
        w_res, b_res, bnres_w, bnres_b, bnres_m, bnres_v,
        w1, b1, bn1_w, bn1_b, bn1_m, bn1_v, w2, b2,
        (float*)d_out);
}